// round 6
// baseline (speedup 1.0000x reference)
#include <cuda_runtime.h>
#include <math.h>
#include <stdint.h>

#define NN (64*4096)      // 262144 nodes
#define NE (64*16384)     // 1048576 edges
#define NS (64*1024)      // 65536 sampled rows
#define IN_F 26

typedef unsigned long long ull;

// scratch (device globals)
__device__ __align__(16) float g_agg[(size_t)NN * 64];
__device__ __align__(16) float g_conv[(size_t)NN * 64];
__device__ __align__(16) float g_P[(size_t)NN * 128];
__device__ unsigned g_flagbits[NN / 32];
__device__ unsigned g_needbits[NN / 32];
__device__ int4  g_sde[NE];
__device__ int   g_nlist[NN];
__device__ int   g_plist[NN];
__device__ int   g_cnt[4];
// pre-converted tf32 weights
__device__ __align__(16) float g_Wl[512 * 512];   // [cell0 Wih|Whh ; cell1 Wih|Whh]
__device__ __align__(16) float g_We_t[64 * 128];
__device__ __align__(16) float g_Wd1_t[256 * 64];
__device__ __align__(16) float g_bc[2 * 512];

// ---------------- packed f32x2 helpers ----------------
__device__ __forceinline__ ull pk(float lo, float hi) {
    ull r; asm("mov.b64 %0, {%1, %2};" : "=l"(r) : "f"(lo), "f"(hi)); return r;
}
__device__ __forceinline__ ull pk2(float v) { return pk(v, v); }
__device__ __forceinline__ float2 upk(ull v) {
    float2 r; asm("mov.b64 {%0, %1}, %2;" : "=f"(r.x), "=f"(r.y) : "l"(v)); return r;
}
__device__ __forceinline__ ull fma2(ull a, ull b, ull c) {
    ull d; asm("fma.rn.f32x2 %0, %1, %2, %3;" : "=l"(d) : "l"(a), "l"(b), "l"(c)); return d;
}
__device__ __forceinline__ ull add2(ull a, ull b) {
    ull d; asm("add.rn.f32x2 %0, %1, %2;" : "=l"(d) : "l"(a), "l"(b)); return d;
}
__device__ __forceinline__ float fsig(float x)  { return __fdividef(1.f, 1.f + __expf(-x)); }
__device__ __forceinline__ float ftanh(float x) { return 1.f - __fdividef(2.f, 1.f + __expf(2.f * x)); }

// ---------------- tf32 mma / cp.async helpers ----------------
__device__ __forceinline__ float tf32v(float f) {
    uint32_t r; asm("cvt.rna.tf32.f32 %0, %1;" : "=r"(r) : "f"(f));
    return __uint_as_float(r);
}
__device__ __forceinline__ void mma8(float* d, const uint32_t* a, uint32_t b0, uint32_t b1) {
    asm volatile(
        "mma.sync.aligned.m16n8k8.row.col.f32.tf32.tf32.f32 "
        "{%0,%1,%2,%3}, {%4,%5,%6,%7}, {%8,%9}, {%0,%1,%2,%3};"
        : "+f"(d[0]), "+f"(d[1]), "+f"(d[2]), "+f"(d[3])
        : "r"(a[0]), "r"(a[1]), "r"(a[2]), "r"(a[3]), "r"(b0), "r"(b1));
}
__device__ __forceinline__ uint32_t ldb(const float* p) { return __float_as_uint(*p); }
__device__ __forceinline__ void cp16(uint32_t dst, const float* src) {
    asm volatile("cp.async.cg.shared.global [%0], [%1], 16;" :: "r"(dst), "l"(src));
}
#define CP_COMMIT() asm volatile("cp.async.commit_group;")
#define CP_WAIT(n)  asm volatile("cp.async.wait_group " #n ";")

// ---------------------------------------------------------------- prep: tf32 weights + zero tables
__global__ __launch_bounds__(256) void prep_kernel(
    const float* __restrict__ Wih0, const float* __restrict__ Whh0,
    const float* __restrict__ Wih1, const float* __restrict__ Whh1,
    const float* __restrict__ We,   const float* __restrict__ Wd1,
    const float* __restrict__ bih0, const float* __restrict__ bhh0,
    const float* __restrict__ bih1, const float* __restrict__ bhh1)
{
    int i = blockIdx.x * 256 + threadIdx.x;
    if (i < 262144) {
        int cell = i >> 17, r = (i >> 9) & 255, n = i & 511;
        const float* W = (r < 128) ? (cell ? Wih1 : Wih0) : (cell ? Whh1 : Whh0);
        g_Wl[i] = tf32v(W[(r & 127) * 512 + n]);
    } else if (i < 270336) {
        int j = i - 262144; g_We_t[j] = tf32v(We[j]);
    } else if (i < 286720) {
        int j = i - 270336; g_Wd1_t[j] = tf32v(Wd1[j]);
    } else if (i < 287744) {
        int j = i - 286720; int cell = j >> 9; int n = j & 511;
        g_bc[j] = cell ? (bih1[n] + bhh1[n]) : (bih0[n] + bhh0[n]);
    } else if (i < 287744 + 8192) {
        g_flagbits[i - 287744] = 0u;
    } else if (i < 287744 + 16384) {
        g_needbits[i - 287744 - 8192] = 0u;
    } else if (i < 287744 + 16384 + 4) {
        g_cnt[i - 287744 - 16384] = 0;
    }
}

// ---------------------------------------------------------------- flag + zero agg rows (warp/sample)
__global__ __launch_bounds__(256) void flag_zero_kernel(const int* __restrict__ si) {
    int gw = blockIdx.x * 8 + (threadIdx.x >> 5);
    int l  = threadIdx.x & 31;
    int n  = si[gw];
    if (l == 0) atomicOr(&g_flagbits[n >> 5], 1u << (n & 31));
    ((float2*)(g_agg + (size_t)n * 64))[l] = make_float2(0.f, 0.f);
}

// ---------------------------------------------------------------- edge compaction (bit flags)
__global__ __launch_bounds__(256) void compact_edges_kernel(const int* __restrict__ ei) {
    int e = blockIdx.x * 256 + threadIdx.x;
    int d = ei[NE + e];
    bool act = (g_flagbits[d >> 5] >> (d & 31)) & 1u;
    unsigned m = __ballot_sync(0xffffffffu, act);
    if (m) {
        int lane = threadIdx.x & 31;
        int leader = __ffs(m) - 1;
        int pos = 0;
        if (lane == leader) pos = atomicAdd(&g_cnt[0], __popc(m));
        pos = __shfl_sync(0xffffffffu, pos, leader);
        pos += __popc(m & ((1u << lane) - 1));
        if (act) {
            int s = ei[e];
            g_sde[pos] = make_int4(s, d, e, 0);
            atomicOr(&g_needbits[s >> 5], 1u << (s & 31));
            atomicOr(&g_needbits[d >> 5], 1u << (d & 31));
        }
    }
}

// ---------------------------------------------------------------- node compaction
__global__ __launch_bounds__(256) void compact_nodes_kernel() {
    int n = blockIdx.x * 256 + threadIdx.x;
    int lane = threadIdx.x & 31;
    {
        bool a = (g_flagbits[n >> 5] >> (n & 31)) & 1u;
        unsigned m = __ballot_sync(0xffffffffu, a);
        if (m) {
            int leader = __ffs(m) - 1;
            int pos = 0;
            if (lane == leader) pos = atomicAdd(&g_cnt[1], __popc(m));
            pos = __shfl_sync(0xffffffffu, pos, leader);
            pos += __popc(m & ((1u << lane) - 1));
            if (a) g_nlist[pos] = n;
        }
    }
    {
        bool a = (g_needbits[n >> 5] >> (n & 31)) & 1u;
        unsigned m = __ballot_sync(0xffffffffu, a);
        if (m) {
            int leader = __ffs(m) - 1;
            int pos = 0;
            if (lane == leader) pos = atomicAdd(&g_cnt[2], __popc(m));
            pos = __shfl_sync(0xffffffffu, pos, leader);
            pos += __popc(m & ((1u << lane) - 1));
            if (a) g_plist[pos] = n;
        }
    }
}

// ---------------------------------------------------------------- per-node edge precompute
__global__ __launch_bounds__(256) void pre_kernel(
    const float* __restrict__ x, const float* __restrict__ Wm,
    const float* __restrict__ bm)
{
    __shared__ float Ws[52 * 64];
    __shared__ float bs[64];
    for (int i = threadIdx.x; i < 52 * 64; i += 256) Ws[i] = Wm[i];
    if (threadIdx.x < 64) bs[threadIdx.x] = bm[threadIdx.x];
    __syncthreads();

    int gid = blockIdx.x * 256 + threadIdx.x;
    int i    = gid >> 1;
    if (i >= g_cnt[2]) return;
    int n    = g_plist[i];
    int half = gid & 1;

    ull acc[32];
#pragma unroll
    for (int j = 0; j < 32; j++)
        acc[j] = half ? 0ull : pk(bs[2 * j], bs[2 * j + 1]);

    const float2* xr = (const float2*)(x + (size_t)n * IN_F);
    const int rbase = half * IN_F;
#pragma unroll
    for (int kk = 0; kk < 13; kk++) {
        float2 xv = xr[kk];
#pragma unroll
        for (int h = 0; h < 2; h++) {
            ull v = pk2(h ? xv.y : xv.x);
            const ulonglong2* wr = (const ulonglong2*)&Ws[(rbase + 2 * kk + h) * 64];
#pragma unroll
            for (int j = 0; j < 16; j++) {
                ulonglong2 w = wr[j];
                acc[2 * j]     = fma2(v, w.x, acc[2 * j]);
                acc[2 * j + 1] = fma2(v, w.y, acc[2 * j + 1]);
            }
        }
    }
    float4* dst = (float4*)(g_P + (size_t)n * 128 + half * 64);
#pragma unroll
    for (int j = 0; j < 16; j++) {
        float2 a = upk(acc[2 * j]), b = upk(acc[2 * j + 1]);
        dst[j] = make_float4(a.x, a.y, b.x, b.y);
    }
}

// ---------------------------------------------------------------- edges (active only)
__global__ __launch_bounds__(256) void edge_kernel(const float* __restrict__ ea,
                                                   const float* __restrict__ Wm)
{
    __shared__ float Ws[15 * 64];
    for (int i = threadIdx.x; i < 15 * 64; i += 256) Ws[i] = Wm[52 * 64 + i];
    __syncthreads();

    const int l  = threadIdx.x & 31;
    const int gw = blockIdx.x * 8 + (threadIdx.x >> 5);
    const int W  = gridDim.x * 8;
    const int ec = g_cnt[0];

    for (int i = gw; i < ec; i += W) {
        int4 sde = g_sde[i];
        ull ps = *(const ull*)(g_P + (size_t)sde.x * 128 + 2 * l);
        ull pd = *(const ull*)(g_P + (size_t)sde.y * 128 + 64 + 2 * l);
        ull acc = add2(ps, pd);
        const float* er = ea + (size_t)sde.z * 15;
#pragma unroll
        for (int k = 0; k < 15; k++) {
            ull w = *(const ull*)&Ws[k * 64 + 2 * l];
            acc = fma2(pk2(er[k]), w, acc);
        }
        float2 a = upk(acc);
        float* ag = g_agg + (size_t)sde.y * 64 + 2 * l;
        atomicAdd(ag,     fmaxf(a.x, 0.f));
        atomicAdd(ag + 1, fmaxf(a.y, 0.f));
    }
}

// ---------------------------------------------------------------- nodes (sampled only)
__global__ __launch_bounds__(256) void node_kernel(
    const float* __restrict__ x, const float* __restrict__ Wn,
    const float* __restrict__ bn)
{
    __shared__ float Ws[90 * 64];
    __shared__ float bs[64];
    for (int i = threadIdx.x; i < 90 * 64; i += 256) Ws[i] = Wn[i];
    if (threadIdx.x < 64) bs[threadIdx.x] = bn[threadIdx.x];
    __syncthreads();

    int i = blockIdx.x * 256 + threadIdx.x;
    if (i >= g_cnt[1]) return;
    int n = g_nlist[i];

    ull acc[32];
#pragma unroll
    for (int j = 0; j < 32; j++) acc[j] = pk(bs[2 * j], bs[2 * j + 1]);

    const float2* xr = (const float2*)(x + (size_t)n * IN_F);
#pragma unroll
    for (int kk = 0; kk < 13; kk++) {
        float2 xv = xr[kk];
#pragma unroll
        for (int h = 0; h < 2; h++) {
            ull v = pk2(h ? xv.y : xv.x);
            const ulonglong2* wr = (const ulonglong2*)&Ws[(2 * kk + h) * 64];
#pragma unroll
            for (int j = 0; j < 16; j++) {
                ulonglong2 w = wr[j];
                acc[2 * j]     = fma2(v, w.x, acc[2 * j]);
                acc[2 * j + 1] = fma2(v, w.y, acc[2 * j + 1]);
            }
        }
    }
    const float4* ar = (const float4*)(g_agg + (size_t)n * 64);
#pragma unroll
    for (int kk = 0; kk < 16; kk++) {
        float4 av = ar[kk];
#pragma unroll
        for (int h = 0; h < 4; h++) {
            float vf = h == 0 ? av.x : h == 1 ? av.y : h == 2 ? av.z : av.w;
            ull v = pk2(vf);
            const ulonglong2* wr = (const ulonglong2*)&Ws[(IN_F + 4 * kk + h) * 64];
#pragma unroll
            for (int j = 0; j < 16; j++) {
                ulonglong2 w = wr[j];
                acc[2 * j]     = fma2(v, w.x, acc[2 * j]);
                acc[2 * j + 1] = fma2(v, w.y, acc[2 * j + 1]);
            }
        }
    }
    float4* dst = (float4*)(g_conv + (size_t)n * 64);
#pragma unroll
    for (int j = 0; j < 16; j++) {
        float2 a = upk(acc[2 * j]), b = upk(acc[2 * j + 1]);
        dst[j] = make_float4(fmaxf(a.x, 0.f), fmaxf(a.y, 0.f),
                             fmaxf(b.x, 0.f), fmaxf(b.y, 0.f));
    }
}

// ---------------------------------------------------------------- fused sampled pipeline
// 64 rows/CTA, 512 threads (16 warps). Unified 52-stage weight stream, 3 buffers, 1 sync/stage.
// stages: 0-3 encoder (We rows 16c..), 4-35 LSTM (cell = (c-4)/16), 36-51 decoder.
#define O_NCT 0            // [64][68]
#define O_A2  4352         // [64][20]
#define O_XT  5632         // [64][132]
#define O_HT  14080        // [64][132]
#define O_B2  22528        // [16][136]
#define O_WST 24704        // 3 x [16][520]
#define WBUF  8320
#define SMEM_F 49664       // 198656 bytes

__global__ __launch_bounds__(512, 1) void sample_kernel(
    const int* __restrict__ sidx_g, const float* __restrict__ gm,
    const float* __restrict__ be,
    const float* __restrict__ bd1,
    const float* __restrict__ Wd2, const float* __restrict__ bd2,
    float* __restrict__ out)
{
    extern __shared__ float sm[];
    float* nct = sm + O_NCT;
    float* A2  = sm + O_A2;
    float* Xt  = sm + O_XT;
    float* Ht  = sm + O_HT;
    float* B2  = sm + O_B2;
    float* Wst = sm + O_WST;
    __shared__ float gmrow[10];
    __shared__ int   sidx[64];

    const int t    = threadIdx.x;
    const int base = blockIdx.x * 64;
    const uint32_t wst_u = (uint32_t)__cvta_generic_to_shared(Wst);

    if (t < 64) sidx[t] = sidx_g[base + t];
    if (t < 10) gmrow[t] = gm[(blockIdx.x >> 4) * 10 + t];
    __syncthreads();

    float* out_nc = out;
    float* out_h1 = out + (size_t)NS * 64;
    float* out_c1 = out_h1 + (size_t)NS * 128;
    float* out_h2 = out_c1 + (size_t)NS * 128;
    float* out_c2 = out_h2 + (size_t)NS * 128;
    float* out_y  = out_c2 + (size_t)NS * 128;

    // B2: We rows 54..63, zero-padded to 16 rows (already tf32 in g_We_t)
    for (int idx = t; idx < 16 * 136; idx += 512) {
        int kk = idx / 136, n = idx - kk * 136;
        B2[idx] = (kk < 10 && n < 128) ? g_We_t[(54 + kk) * 128 + n] : 0.f;
    }
    // gather node_conv (tf32) + out_nc (exact) + A2
    for (int idx = t; idx < 64 * 64; idx += 512) {
        int r = idx >> 6, c = idx & 63;
        float v = g_conv[(size_t)sidx[r] * 64 + c];
        nct[r * 68 + c] = tf32v(v);
        out_nc[(size_t)(base + r) * 64 + c] = v;
    }
    for (int idx = t; idx < 64 * 20; idx += 512) {
        int r = idx / 20, kk = idx - r * 20;
        A2[idx] = (kk < 10) ? tf32v(g_conv[(size_t)sidx[r] * 64 + 54 + kk]) : 0.f;
    }

    // prefetch helper (chunk c2 -> buffer c2%3)
    auto prefetch = [&](int c2) {
        uint32_t db = wst_u + (uint32_t)((c2 % 3) * WBUF) * 4;
        if (c2 < 4) {
            int bpos = t * 4; int kk = bpos >> 7, n = bpos & 127;
            cp16(db + (uint32_t)(kk * 520 + n) * 4, g_We_t + c2 * 2048 + kk * 128 + n);
        } else if (c2 < 36) {
#pragma unroll
            for (int ii = 0; ii < 4; ii++) {
                int bpos = (ii * 512 + t) * 4; int kk = bpos >> 9, n = bpos & 511;
                cp16(db + (uint32_t)(kk * 520 + n) * 4,
                     g_Wl + (size_t)(c2 - 4) * 8192 + kk * 512 + n);
            }
        } else if (c2 < 52) {
            if (t < 256) {
                int bpos = t * 4; int kk = bpos >> 6, n = bpos & 63;
                cp16(db + (uint32_t)(kk * 520 + n) * 4,
                     g_Wd1_t + (c2 - 36) * 1024 + kk * 64 + n);
            }
        }
        CP_COMMIT();
    };
    prefetch(0);
    prefetch(1);

    const int w    = t >> 5;
    const int lane = t & 31;
    const int g8   = lane >> 2;
    const int cc   = lane & 3;
    const int j0   = w * 8;
    const int col0 = j0 + 2 * cc, col1 = col0 + 1;

    float acc[64];
#pragma unroll
    for (int i = 0; i < 64; i++) acc[i] = 0.f;

    // LSTM epilogue lambda: cell = 0 or 1
    auto lstm_epi = [&](int cell) {
        const float* bc = g_bc + cell * 512;
        float* oH = cell ? out_h2 : out_h1;
        float* oC = cell ? out_c2 : out_c1;
        float bi0 = bc[col0],       bi1 = bc[col1];
        float bf0 = bc[128 + col0], bf1 = bc[128 + col1];
        float bg0 = bc[256 + col0], bg1 = bc[256 + col1];
        float bo0 = bc[384 + col0], bo1 = bc[384 + col1];
#pragma unroll
        for (int mt = 0; mt < 4; mt++) {
#pragma unroll
            for (int pp = 0; pp < 2; pp++) {
                int row = mt * 16 + g8 + pp * 8;
                int ib  = mt * 16 + pp * 2;
                float vi0 = acc[ib + 0]  + bi0, vi1 = acc[ib + 1]  + bi1;
                float vf0 = acc[ib + 4]  + bf0, vf1 = acc[ib + 5]  + bf1;
                float vg0 = acc[ib + 8]  + bg0, vg1 = acc[ib + 9]  + bg1;
                float vo0 = acc[ib + 12] + bo0, vo1 = acc[ib + 13] + bo1;
                float cp0 = Ht[row * 132 + col0], cp1 = Ht[row * 132 + col1];
                float cv0 = fsig(vf0) * cp0 + fsig(vi0) * ftanh(vg0);
                float cv1 = fsig(vf1) * cp1 + fsig(vi1) * ftanh(vg1);
                float hv0 = fsig(vo0) * ftanh(cv0);
                float hv1 = fsig(vo1) * ftanh(cv1);
                size_t gi = (size_t)(base + row) * 128 + col0;
                *(float2*)(oH + gi) = make_float2(hv0, hv1);
                *(float2*)(oC + gi) = make_float2(cv0, cv1);
                if (cell == 0) {
                    float nx0 = (col0 >= 118) ? gmrow[col0 - 118] : hv0;
                    float nx1 = (col1 >= 118) ? gmrow[col1 - 118] : hv1;
                    *(float2*)(Xt + row * 132 + col0) = make_float2(tf32v(nx0), tf32v(nx1));
                } else {
                    *(float2*)(Xt + row * 132 + col0) = make_float2(tf32v(hv0), tf32v(hv1));
                    *(float2*)(Ht + row * 132 + col0) = make_float2(tf32v(cv0), tf32v(cv1));
                }
            }
        }
#pragma unroll
        for (int i = 0; i < 64; i++) acc[i] = 0.f;
    };

    // ================= unified 52-stage pipeline =================
#pragma unroll 1
    for (int c = 0; c < 52; c++) {
        CP_WAIT(1);
        __syncthreads();

        if (c == 20) { lstm_epi(0); __syncthreads(); }
        if (c == 36) { lstm_epi(1); __syncthreads(); }

        prefetch(c + 2);

        const float* wb = Wst + (c % 3) * WBUF;
        if (c < 4) {
            // encoder chunk: We rows c*16..c*16+15, A = nct cols
#pragma unroll
            for (int ks = 0; ks < 2; ks++) {
                int k0 = c * 16 + ks * 8;
                uint32_t b0 = ldb(&wb[(ks * 8 + cc) * 520 + j0 + g8]);
                uint32_t b1 = ldb(&wb[(ks * 8 + cc + 4) * 520 + j0 + g8]);
#pragma unroll
                for (int mt = 0; mt < 4; mt++) {
                    int r0 = mt * 16 + g8;
                    uint32_t a[4];
                    a[0] = ldb(&nct[r0 * 68 + k0 + cc]);
                    a[1] = ldb(&nct[(r0 + 8) * 68 + k0 + cc]);
                    a[2] = ldb(&nct[r0 * 68 + k0 + cc + 4]);
                    a[3] = ldb(&nct[(r0 + 8) * 68 + k0 + cc + 4]);
                    mma8(acc + mt * 4, a, b0, b1);
                }
            }
            if (c == 3) {
                // correction mma (B2/A2) into acc[16..31]
#pragma unroll
                for (int ks = 0; ks < 2; ks++) {
                    int k0 = ks * 8;
                    uint32_t b0 = ldb(&B2[(k0 + cc) * 136 + j0 + g8]);
                    uint32_t b1 = ldb(&B2[(k0 + cc + 4) * 136 + j0 + g8]);
#pragma unroll
                    for (int mt = 0; mt < 4; mt++) {
                        int r0 = mt * 16 + g8;
                        uint32_t a[4];
                        a[0] = ldb(&A2[r0 * 20 + k0 + cc]);
                        a[1] = ldb(&A2[(r0 + 8) * 20 + k0 + cc]);
                        a[2] = ldb(&A2[r0 * 20 + k0 + cc + 4]);
                        a[3] = ldb(&A2[(r0 + 8) * 20 + k0 + cc + 4]);
                        mma8(acc + 16 + mt * 4, a, b0, b1);
                    }
                }
                // encoder epilogue
                float be0 = be[col0], be1 = be[col1];
                float gs0 = 0.f, gs1 = 0.f;
#pragma unroll
                for (int k = 0; k < 10; k++) {
                    gs0 = fmaf(gmrow[k], B2[k * 136 + col0], gs0);
                    gs1 = fmaf(gmrow[k], B2[k * 136 + col1], gs1);
                }
#pragma unroll
                for (int mt = 0; mt < 4; mt++) {
#pragma unroll
                    for (int pp = 0; pp < 2; pp++) {
                        int row = mt * 16 + g8 + pp * 8;
                        float hp0 = acc[mt * 4 + pp * 2],     hp1 = acc[mt * 4 + pp * 2 + 1];
                        float cr0 = acc[16 + mt * 4 + pp * 2], cr1 = acc[16 + mt * 4 + pp * 2 + 1];
                        float X0 = fmaxf(hp0 - cr0 + gs0 + be0, 0.f);
                        float X1 = fmaxf(hp1 - cr1 + gs1 + be1, 0.f);
                        float H0 = fmaxf(hp0 + be0, 0.f);
                        float H1 = fmaxf(hp1 + be1, 0.f);
                        *(float2*)(Xt + row * 132 + col0) = make_float2(tf32v(X0), tf32v(X1));
                        *(float2*)(Ht + row * 132 + col0) = make_float2(tf32v(H0), tf32v(H1));
                    }
                }
#pragma unroll
                for (int i = 0; i < 64; i++) acc[i] = 0.f;
            }
        } else if (c < 36) {
            // LSTM chunk
            const int kl = ((c - 4) & 15) * 16;
#pragma unroll
            for (int ks = 0; ks < 2; ks++) {
                int kg = kl + ks * 8;
                const float* At_ = (kg < 128) ? (Xt + kg) : (Ht + (kg - 128));
                uint32_t afr[4][4];
#pragma unroll
                for (int mt = 0; mt < 4; mt++) {
                    int r0 = mt * 16 + g8;
                    afr[mt][0] = ldb(&At_[r0 * 132 + cc]);
                    afr[mt][1] = ldb(&At_[(r0 + 8) * 132 + cc]);
                    afr[mt][2] = ldb(&At_[r0 * 132 + cc + 4]);
                    afr[mt][3] = ldb(&At_[(r0 + 8) * 132 + cc + 4]);
                }
#pragma unroll
                for (int q = 0; q < 4; q++) {
                    int ncol = q * 128 + j0 + g8;
                    uint32_t b0 = ldb(&wb[(ks * 8 + cc) * 520 + ncol]);
                    uint32_t b1 = ldb(&wb[(ks * 8 + cc + 4) * 520 + ncol]);
#pragma unroll
                    for (int mt = 0; mt < 4; mt++)
                        mma8(acc + mt * 16 + q * 4, afr[mt], b0, b1);
                }
            }
        } else {
            // decoder chunk: warp w -> n-tile (w&7), m-tiles 2*(w>>3)..+1
            const int n0  = (w & 7) * 8;
            const int mt0 = (w >> 3) * 2;
#pragma unroll
            for (int ks = 0; ks < 2; ks++) {
                int kg = (c - 36) * 16 + ks * 8;
                const float* At_ = (kg < 128) ? (Xt + kg) : (Ht + (kg - 128));
                uint32_t b0 = ldb(&wb[(ks * 8 + cc) * 520 + n0 + g8]);
                uint32_t b1 = ldb(&wb[(ks * 8 + cc + 4) * 520 + n0 + g8]);
#pragma unroll
                for (int m = 0; m < 2; m++) {
                    int r0 = (mt0 + m) * 16 + g8;
                    uint32_t a[4];
                    a[0] = ldb(&At_[r0 * 132 + cc]);
                    a[1] = ldb(&At_[(r0 + 8) * 132 + cc]);
                    a[2] = ldb(&At_[r0 * 132 + cc + 4]);
                    a[3] = ldb(&At_[(r0 + 8) * 132 + cc + 4]);
                    mma8(acc + m * 4, a, b0, b1);
                }
            }
        }
    }

    // decoder epilogue -> nct as d1 (row-major, stride 68)
    {
        const int n0  = (w & 7) * 8;
        const int mt0 = (w >> 3) * 2;
        int c0 = n0 + 2 * cc, c1 = c0 + 1;
        float b0 = bd1[c0], b1 = bd1[c1];
#pragma unroll
        for (int m = 0; m < 2; m++) {
#pragma unroll
            for (int pp = 0; pp < 2; pp++) {
                int row = (mt0 + m) * 16 + g8 + pp * 8;
                float v0 = fmaxf(acc[m * 4 + pp * 2]     + b0, 0.f);
                float v1 = fmaxf(acc[m * 4 + pp * 2 + 1] + b1, 0.f);
                *(float2*)(nct + row * 68 + c0) = make_float2(v0, v1);
            }
        }
    }
    __syncthreads();

    // y = d1 @ Wd2 + b
    if (t < 384) {
        int r = t / 6, c = t - r * 6;
        float accy = bd2[c];
#pragma unroll
        for (int k = 0; k < 64; k++) accy = fmaf(nct[r * 68 + k], Wd2[k * 6 + c], accy);
        out_y[(size_t)(base + r) * 6 + c] = accy;
    }
}

// ----------------------------------------------------------------
extern "C" void kernel_launch(void* const* d_in, const int* in_sizes, int n_in,
                              void* d_out, int out_size)
{
    const float* x    = (const float*)d_in[0];
    const int*   ei   = (const int*)d_in[1];
    const float* ea   = (const float*)d_in[2];
    const int*   si   = (const int*)d_in[3];
    const float* gm   = (const float*)d_in[4];
    const float* Wm   = (const float*)d_in[5];
    const float* bm   = (const float*)d_in[6];
    const float* Wn   = (const float*)d_in[7];
    const float* bn   = (const float*)d_in[8];
    const float* We   = (const float*)d_in[9];
    const float* be_  = (const float*)d_in[10];
    const float* Wih0 = (const float*)d_in[11];
    const float* Whh0 = (const float*)d_in[12];
    const float* bih0 = (const float*)d_in[13];
    const float* bhh0 = (const float*)d_in[14];
    const float* Wih1 = (const float*)d_in[15];
    const float* Whh1 = (const float*)d_in[16];
    const float* bih1 = (const float*)d_in[17];
    const float* bhh1 = (const float*)d_in[18];
    const float* Wd1  = (const float*)d_in[19];
    const float* bd1  = (const float*)d_in[20];
    const float* Wd2  = (const float*)d_in[21];
    const float* bd2  = (const float*)d_in[22];
    float* out = (float*)d_out;

    const int smem_bytes = SMEM_F * 4;   // 198656
    cudaFuncSetAttribute(sample_kernel,
                         cudaFuncAttributeMaxDynamicSharedMemorySize, smem_bytes);

    prep_kernel<<<1189, 256>>>(Wih0, Whh0, Wih1, Whh1, We, Wd1, bih0, bhh0, bih1, bhh1);
    flag_zero_kernel<<<NS / 8, 256>>>(si);
    compact_edges_kernel<<<NE / 256, 256>>>(ei);
    compact_nodes_kernel<<<NN / 256, 256>>>();
    pre_kernel<<<2 * NN / 256, 256>>>(x, Wm, bm);
    edge_kernel<<<1024, 256>>>(ea, Wm);
    node_kernel<<<NS / 256, 256>>>(x, Wn, bn);
    sample_kernel<<<NS / 64, 512, smem_bytes>>>(
        si, gm, be_, bd1, Wd2, bd2, out);
}

// round 7
// speedup vs baseline: 1.1478x; 1.1478x over previous
#include <cuda_runtime.h>
#include <math.h>
#include <stdint.h>

#define NN (64*4096)      // 262144 nodes
#define NE (64*16384)     // 1048576 edges
#define NS (64*1024)      // 65536 sampled rows
#define IN_F 26

typedef unsigned long long ull;

// scratch (device globals)
__device__ __align__(16) float g_agg[(size_t)NN * 64];
__device__ __align__(16) float g_conv[(size_t)NN * 64];
__device__ __align__(16) float g_P[(size_t)NN * 128];
__device__ unsigned g_flagbits[NN / 32];
__device__ unsigned g_needbits[NN / 32];
__device__ int4  g_sde[NE];
__device__ int   g_nlist[NN];
__device__ int   g_plist[NN];
__device__ int   g_cnt[4];
// pre-converted tf32 weights
__device__ __align__(16) float g_Wl[512 * 512];   // [cell0 Wih|Whh ; cell1 Wih|Whh]
__device__ __align__(16) float g_We_t[64 * 128];
__device__ __align__(16) float g_Wd1_t[256 * 64];
__device__ __align__(16) float g_bc[2 * 512];

// ---------------- packed f32x2 helpers ----------------
__device__ __forceinline__ ull pk(float lo, float hi) {
    ull r; asm("mov.b64 %0, {%1, %2};" : "=l"(r) : "f"(lo), "f"(hi)); return r;
}
__device__ __forceinline__ ull pk2(float v) { return pk(v, v); }
__device__ __forceinline__ float2 upk(ull v) {
    float2 r; asm("mov.b64 {%0, %1}, %2;" : "=f"(r.x), "=f"(r.y) : "l"(v)); return r;
}
__device__ __forceinline__ ull fma2(ull a, ull b, ull c) {
    ull d; asm("fma.rn.f32x2 %0, %1, %2, %3;" : "=l"(d) : "l"(a), "l"(b), "l"(c)); return d;
}
__device__ __forceinline__ ull add2(ull a, ull b) {
    ull d; asm("add.rn.f32x2 %0, %1, %2;" : "=l"(d) : "l"(a), "l"(b)); return d;
}
__device__ __forceinline__ float fsig(float x)  { return __fdividef(1.f, 1.f + __expf(-x)); }
__device__ __forceinline__ float ftanh(float x) { return 1.f - __fdividef(2.f, 1.f + __expf(2.f * x)); }

// ---------------- tf32 mma / cp.async helpers ----------------
__device__ __forceinline__ float tf32v(float f) {
    uint32_t r; asm("cvt.rna.tf32.f32 %0, %1;" : "=r"(r) : "f"(f));
    return __uint_as_float(r);
}
__device__ __forceinline__ void mma8(float* d, const uint32_t* a, uint32_t b0, uint32_t b1) {
    asm volatile(
        "mma.sync.aligned.m16n8k8.row.col.f32.tf32.tf32.f32 "
        "{%0,%1,%2,%3}, {%4,%5,%6,%7}, {%8,%9}, {%0,%1,%2,%3};"
        : "+f"(d[0]), "+f"(d[1]), "+f"(d[2]), "+f"(d[3])
        : "r"(a[0]), "r"(a[1]), "r"(a[2]), "r"(a[3]), "r"(b0), "r"(b1));
}
__device__ __forceinline__ uint32_t ldb(const float* p) { return __float_as_uint(*p); }
__device__ __forceinline__ void cp16(uint32_t dst, const float* src) {
    asm volatile("cp.async.cg.shared.global [%0], [%1], 16;" :: "r"(dst), "l"(src));
}
#define CP_COMMIT() asm volatile("cp.async.commit_group;")
#define CP_WAIT(n)  asm volatile("cp.async.wait_group " #n ";")

// ---------------------------------------------------------------- prep: tf32 weights + zero tables
__global__ __launch_bounds__(256) void prep_kernel(
    const float* __restrict__ Wih0, const float* __restrict__ Whh0,
    const float* __restrict__ Wih1, const float* __restrict__ Whh1,
    const float* __restrict__ We,   const float* __restrict__ Wd1,
    const float* __restrict__ bih0, const float* __restrict__ bhh0,
    const float* __restrict__ bih1, const float* __restrict__ bhh1)
{
    int i = blockIdx.x * 256 + threadIdx.x;
    if (i < 262144) {
        int cell = i >> 17, r = (i >> 9) & 255, n = i & 511;
        const float* W = (r < 128) ? (cell ? Wih1 : Wih0) : (cell ? Whh1 : Whh0);
        g_Wl[i] = tf32v(W[(r & 127) * 512 + n]);
    } else if (i < 270336) {
        int j = i - 262144; g_We_t[j] = tf32v(We[j]);
    } else if (i < 286720) {
        int j = i - 270336; g_Wd1_t[j] = tf32v(Wd1[j]);
    } else if (i < 287744) {
        int j = i - 286720; int cell = j >> 9; int n = j & 511;
        g_bc[j] = cell ? (bih1[n] + bhh1[n]) : (bih0[n] + bhh0[n]);
    } else if (i < 287744 + 8192) {
        g_flagbits[i - 287744] = 0u;
    } else if (i < 287744 + 16384) {
        g_needbits[i - 287744 - 8192] = 0u;
    } else if (i < 287744 + 16384 + 4) {
        g_cnt[i - 287744 - 16384] = 0;
    }
}

// ---------------------------------------------------------------- flag + zero agg rows (warp/sample)
__global__ __launch_bounds__(256) void flag_zero_kernel(const int* __restrict__ si) {
    int gw = blockIdx.x * 8 + (threadIdx.x >> 5);
    int l  = threadIdx.x & 31;
    int n  = si[gw];
    if (l == 0) atomicOr(&g_flagbits[n >> 5], 1u << (n & 31));
    ((float2*)(g_agg + (size_t)n * 64))[l] = make_float2(0.f, 0.f);
}

// ---------------------------------------------------------------- edge compaction (bit flags)
__global__ __launch_bounds__(256) void compact_edges_kernel(const int* __restrict__ ei) {
    int e = blockIdx.x * 256 + threadIdx.x;
    int d = ei[NE + e];
    bool act = (g_flagbits[d >> 5] >> (d & 31)) & 1u;
    unsigned m = __ballot_sync(0xffffffffu, act);
    if (m) {
        int lane = threadIdx.x & 31;
        int leader = __ffs(m) - 1;
        int pos = 0;
        if (lane == leader) pos = atomicAdd(&g_cnt[0], __popc(m));
        pos = __shfl_sync(0xffffffffu, pos, leader);
        pos += __popc(m & ((1u << lane) - 1));
        if (act) {
            int s = ei[e];
            g_sde[pos] = make_int4(s, d, e, 0);
            atomicOr(&g_needbits[s >> 5], 1u << (s & 31));
            atomicOr(&g_needbits[d >> 5], 1u << (d & 31));
        }
    }
}

// ---------------------------------------------------------------- node compaction
__global__ __launch_bounds__(256) void compact_nodes_kernel() {
    int n = blockIdx.x * 256 + threadIdx.x;
    int lane = threadIdx.x & 31;
    {
        bool a = (g_flagbits[n >> 5] >> (n & 31)) & 1u;
        unsigned m = __ballot_sync(0xffffffffu, a);
        if (m) {
            int leader = __ffs(m) - 1;
            int pos = 0;
            if (lane == leader) pos = atomicAdd(&g_cnt[1], __popc(m));
            pos = __shfl_sync(0xffffffffu, pos, leader);
            pos += __popc(m & ((1u << lane) - 1));
            if (a) g_nlist[pos] = n;
        }
    }
    {
        bool a = (g_needbits[n >> 5] >> (n & 31)) & 1u;
        unsigned m = __ballot_sync(0xffffffffu, a);
        if (m) {
            int leader = __ffs(m) - 1;
            int pos = 0;
            if (lane == leader) pos = atomicAdd(&g_cnt[2], __popc(m));
            pos = __shfl_sync(0xffffffffu, pos, leader);
            pos += __popc(m & ((1u << lane) - 1));
            if (a) g_plist[pos] = n;
        }
    }
}

// ---------------------------------------------------------------- per-node edge precompute
__global__ __launch_bounds__(256) void pre_kernel(
    const float* __restrict__ x, const float* __restrict__ Wm,
    const float* __restrict__ bm)
{
    __shared__ float Ws[52 * 64];
    __shared__ float bs[64];
    for (int i = threadIdx.x; i < 52 * 64; i += 256) Ws[i] = Wm[i];
    if (threadIdx.x < 64) bs[threadIdx.x] = bm[threadIdx.x];
    __syncthreads();

    int gid = blockIdx.x * 256 + threadIdx.x;
    int i    = gid >> 1;
    if (i >= g_cnt[2]) return;
    int n    = g_plist[i];
    int half = gid & 1;

    ull acc[32];
#pragma unroll
    for (int j = 0; j < 32; j++)
        acc[j] = half ? 0ull : pk(bs[2 * j], bs[2 * j + 1]);

    const float2* xr = (const float2*)(x + (size_t)n * IN_F);
    const int rbase = half * IN_F;
#pragma unroll
    for (int kk = 0; kk < 13; kk++) {
        float2 xv = xr[kk];
#pragma unroll
        for (int h = 0; h < 2; h++) {
            ull v = pk2(h ? xv.y : xv.x);
            const ulonglong2* wr = (const ulonglong2*)&Ws[(rbase + 2 * kk + h) * 64];
#pragma unroll
            for (int j = 0; j < 16; j++) {
                ulonglong2 w = wr[j];
                acc[2 * j]     = fma2(v, w.x, acc[2 * j]);
                acc[2 * j + 1] = fma2(v, w.y, acc[2 * j + 1]);
            }
        }
    }
    float4* dst = (float4*)(g_P + (size_t)n * 128 + half * 64);
#pragma unroll
    for (int j = 0; j < 16; j++) {
        float2 a = upk(acc[2 * j]), b = upk(acc[2 * j + 1]);
        dst[j] = make_float4(a.x, a.y, b.x, b.y);
    }
}

// ---------------------------------------------------------------- edges (active only)
__global__ __launch_bounds__(256) void edge_kernel(const float* __restrict__ ea,
                                                   const float* __restrict__ Wm)
{
    __shared__ float Ws[15 * 64];
    for (int i = threadIdx.x; i < 15 * 64; i += 256) Ws[i] = Wm[52 * 64 + i];
    __syncthreads();

    const int l  = threadIdx.x & 31;
    const int gw = blockIdx.x * 8 + (threadIdx.x >> 5);
    const int W  = gridDim.x * 8;
    const int ec = g_cnt[0];

    for (int i = gw; i < ec; i += W) {
        int4 sde = g_sde[i];
        ull ps = *(const ull*)(g_P + (size_t)sde.x * 128 + 2 * l);
        ull pd = *(const ull*)(g_P + (size_t)sde.y * 128 + 64 + 2 * l);
        ull acc = add2(ps, pd);
        const float* er = ea + (size_t)sde.z * 15;
#pragma unroll
        for (int k = 0; k < 15; k++) {
            ull w = *(const ull*)&Ws[k * 64 + 2 * l];
            acc = fma2(pk2(er[k]), w, acc);
        }
        float2 a = upk(acc);
        float* ag = g_agg + (size_t)sde.y * 64 + 2 * l;
        atomicAdd(ag,     fmaxf(a.x, 0.f));
        atomicAdd(ag + 1, fmaxf(a.y, 0.f));
    }
}

// ---------------------------------------------------------------- nodes (sampled only)
__global__ __launch_bounds__(256) void node_kernel(
    const float* __restrict__ x, const float* __restrict__ Wn,
    const float* __restrict__ bn)
{
    __shared__ float Ws[90 * 64];
    __shared__ float bs[64];
    for (int i = threadIdx.x; i < 90 * 64; i += 256) Ws[i] = Wn[i];
    if (threadIdx.x < 64) bs[threadIdx.x] = bn[threadIdx.x];
    __syncthreads();

    int i = blockIdx.x * 256 + threadIdx.x;
    if (i >= g_cnt[1]) return;
    int n = g_nlist[i];

    ull acc[32];
#pragma unroll
    for (int j = 0; j < 32; j++) acc[j] = pk(bs[2 * j], bs[2 * j + 1]);

    const float2* xr = (const float2*)(x + (size_t)n * IN_F);
#pragma unroll
    for (int kk = 0; kk < 13; kk++) {
        float2 xv = xr[kk];
#pragma unroll
        for (int h = 0; h < 2; h++) {
            ull v = pk2(h ? xv.y : xv.x);
            const ulonglong2* wr = (const ulonglong2*)&Ws[(2 * kk + h) * 64];
#pragma unroll
            for (int j = 0; j < 16; j++) {
                ulonglong2 w = wr[j];
                acc[2 * j]     = fma2(v, w.x, acc[2 * j]);
                acc[2 * j + 1] = fma2(v, w.y, acc[2 * j + 1]);
            }
        }
    }
    const float4* ar = (const float4*)(g_agg + (size_t)n * 64);
#pragma unroll
    for (int kk = 0; kk < 16; kk++) {
        float4 av = ar[kk];
#pragma unroll
        for (int h = 0; h < 4; h++) {
            float vf = h == 0 ? av.x : h == 1 ? av.y : h == 2 ? av.z : av.w;
            ull v = pk2(vf);
            const ulonglong2* wr = (const ulonglong2*)&Ws[(IN_F + 4 * kk + h) * 64];
#pragma unroll
            for (int j = 0; j < 16; j++) {
                ulonglong2 w = wr[j];
                acc[2 * j]     = fma2(v, w.x, acc[2 * j]);
                acc[2 * j + 1] = fma2(v, w.y, acc[2 * j + 1]);
            }
        }
    }
    float4* dst = (float4*)(g_conv + (size_t)n * 64);
#pragma unroll
    for (int j = 0; j < 16; j++) {
        float2 a = upk(acc[2 * j]), b = upk(acc[2 * j + 1]);
        dst[j] = make_float4(fmaxf(a.x, 0.f), fmaxf(a.y, 0.f),
                             fmaxf(b.x, 0.f), fmaxf(b.y, 0.f));
    }
}

// ---------------------------------------------------------------- fused sampled pipeline (round-5 structure)
// 64 rows/CTA, 512 threads (16 warps).
#define O_NCT 0            // [64][68]   node_conv (tf32); later d1
#define O_A2  4352         // [64][20]   gm-correction A
#define O_XT  5632         // [64][132]  X -> h_gm -> h2
#define O_HT  14080        // [64][132]  H0 -> c2
#define O_ENC 22528        // [64][136]  encoder weights
#define O_B2  31232        // [16][136]  We rows 54..63, zero pad
#define O_WST 33408        // 2 x [16][520] lstm/dec weight double buffer
#define WBUF  8320
#define SMEM_F 50048       // 200192 bytes

__global__ __launch_bounds__(512, 1) void sample_kernel(
    const int* __restrict__ sidx_g, const float* __restrict__ gm,
    const float* __restrict__ be,
    const float* __restrict__ bd1,
    const float* __restrict__ Wd2, const float* __restrict__ bd2,
    float* __restrict__ out)
{
    extern __shared__ float sm[];
    float* nct = sm + O_NCT;
    float* A2  = sm + O_A2;
    float* Xt  = sm + O_XT;
    float* Ht  = sm + O_HT;
    float* Enc = sm + O_ENC;
    float* B2  = sm + O_B2;
    float* Wst = sm + O_WST;
    __shared__ float gmrow[10];
    __shared__ int   sidx[64];

    const int t    = threadIdx.x;
    const int base = blockIdx.x * 64;
    const uint32_t enc_u = (uint32_t)__cvta_generic_to_shared(Enc);
    const uint32_t b2_u  = (uint32_t)__cvta_generic_to_shared(B2);
    const uint32_t wst_u = (uint32_t)__cvta_generic_to_shared(Wst);

    if (t < 64) sidx[t] = sidx_g[base + t];
    if (t < 10) gmrow[t] = gm[(blockIdx.x >> 4) * 10 + t];

    // ---- async stage: encoder weights + B2 (group 1)
#pragma unroll
    for (int ii = 0; ii < 4; ii++) {
        int bpos = (ii * 512 + t) * 4;
        int kk = bpos >> 7, n = bpos & 127;
        cp16(enc_u + (uint32_t)(kk * 136 + n) * 4, g_We_t + bpos);
    }
    if (t < 320) {
        int bpos = t * 4;
        int kk = bpos >> 7, n = bpos & 127;
        cp16(b2_u + (uint32_t)(kk * 136 + n) * 4, g_We_t + (54 + kk) * 128 + n);
    }
    CP_COMMIT();
    // B2 zero pad rows 10..15 (plain STS, disjoint from cp.async region)
    for (int idx = t; idx < 6 * 136; idx += 512) B2[10 * 136 + idx] = 0.f;

    __syncthreads();   // sidx visible

    float* out_nc = out;
    float* out_h1 = out + (size_t)NS * 64;
    float* out_c1 = out_h1 + (size_t)NS * 128;
    float* out_h2 = out_c1 + (size_t)NS * 128;
    float* out_c2 = out_h2 + (size_t)NS * 128;
    float* out_y  = out_c2 + (size_t)NS * 128;

    // ---- gather node_conv (tf32) + out_nc (exact) + A2 (both straight from global)
    for (int idx = t; idx < 64 * 64; idx += 512) {
        int r = idx >> 6, c = idx & 63;
        float v = g_conv[(size_t)sidx[r] * 64 + c];
        nct[r * 68 + c] = tf32v(v);
        out_nc[(size_t)(base + r) * 64 + c] = v;
    }
    for (int idx = t; idx < 64 * 20; idx += 512) {
        int r = idx / 20, kk = idx - r * 20;
        A2[idx] = (kk < 10) ? tf32v(g_conv[(size_t)sidx[r] * 64 + 54 + kk]) : 0.f;
    }

    // ---- stage LSTM chunks 0,1 (groups 2,3)
#pragma unroll
    for (int ii = 0; ii < 4; ii++) {
        int bpos = (ii * 512 + t) * 4;
        int kk = bpos >> 9, n = bpos & 511;
        cp16(wst_u + (uint32_t)(kk * 520 + n) * 4, g_Wl + (size_t)kk * 512 + n);
    }
    CP_COMMIT();
#pragma unroll
    for (int ii = 0; ii < 4; ii++) {
        int bpos = (ii * 512 + t) * 4;
        int kk = bpos >> 9, n = bpos & 511;
        cp16(wst_u + (uint32_t)(WBUF + kk * 520 + n) * 4, g_Wl + (size_t)(16 + kk) * 512 + n);
    }
    CP_COMMIT();

    CP_WAIT(2);         // encoder weights ready
    __syncthreads();

    const int w    = t >> 5;
    const int lane = t & 31;
    const int g8   = lane >> 2;
    const int cc   = lane & 3;
    const int j0   = w * 8;
    const int col0 = j0 + 2 * cc, col1 = col0 + 1;

    // ================= encoder =================
    {
        float accH[16], accC[16];
#pragma unroll
        for (int i = 0; i < 16; i++) { accH[i] = 0.f; accC[i] = 0.f; }
#pragma unroll
        for (int ks = 0; ks < 8; ks++) {
            int k0 = ks * 8;
            uint32_t b0 = ldb(&Enc[(k0 + cc) * 136 + j0 + g8]);
            uint32_t b1 = ldb(&Enc[(k0 + cc + 4) * 136 + j0 + g8]);
#pragma unroll
            for (int mt = 0; mt < 4; mt++) {
                int r0 = mt * 16 + g8;
                uint32_t a[4];
                a[0] = ldb(&nct[r0 * 68 + k0 + cc]);
                a[1] = ldb(&nct[(r0 + 8) * 68 + k0 + cc]);
                a[2] = ldb(&nct[r0 * 68 + k0 + cc + 4]);
                a[3] = ldb(&nct[(r0 + 8) * 68 + k0 + cc + 4]);
                mma8(accH + mt * 4, a, b0, b1);
            }
        }
#pragma unroll
        for (int ks = 0; ks < 2; ks++) {
            int k0 = ks * 8;
            uint32_t b0 = ldb(&B2[(k0 + cc) * 136 + j0 + g8]);
            uint32_t b1 = ldb(&B2[(k0 + cc + 4) * 136 + j0 + g8]);
#pragma unroll
            for (int mt = 0; mt < 4; mt++) {
                int r0 = mt * 16 + g8;
                uint32_t a[4];
                a[0] = ldb(&A2[r0 * 20 + k0 + cc]);
                a[1] = ldb(&A2[(r0 + 8) * 20 + k0 + cc]);
                a[2] = ldb(&A2[r0 * 20 + k0 + cc + 4]);
                a[3] = ldb(&A2[(r0 + 8) * 20 + k0 + cc + 4]);
                mma8(accC + mt * 4, a, b0, b1);
            }
        }
        float be0 = be[col0], be1 = be[col1];
        float gs0 = 0.f, gs1 = 0.f;
#pragma unroll
        for (int k = 0; k < 10; k++) {
            gs0 = fmaf(gmrow[k], B2[k * 136 + col0], gs0);
            gs1 = fmaf(gmrow[k], B2[k * 136 + col1], gs1);
        }
#pragma unroll
        for (int mt = 0; mt < 4; mt++) {
#pragma unroll
            for (int pp = 0; pp < 2; pp++) {
                int row = mt * 16 + g8 + pp * 8;
                float hp0 = accH[mt * 4 + pp * 2],  hp1 = accH[mt * 4 + pp * 2 + 1];
                float cr0 = accC[mt * 4 + pp * 2],  cr1 = accC[mt * 4 + pp * 2 + 1];
                *(float2*)(Xt + row * 132 + col0) =
                    make_float2(tf32v(fmaxf(hp0 - cr0 + gs0 + be0, 0.f)),
                                tf32v(fmaxf(hp1 - cr1 + gs1 + be1, 0.f)));
                *(float2*)(Ht + row * 132 + col0) =
                    make_float2(tf32v(fmaxf(hp0 + be0, 0.f)),
                                tf32v(fmaxf(hp1 + be1, 0.f)));
            }
        }
    }

    // ================= LSTM: flat 32 chunks (cell0: 0-15, cell1: 16-31) =================
    float acc[64];
#pragma unroll
    for (int i = 0; i < 64; i++) acc[i] = 0.f;

#pragma unroll 1
    for (int c = 0; c < 32; c++) {
        const int buf = c & 1;
        CP_WAIT(1);
        __syncthreads();

        if (c == 16) {
            // ---- cell0 epilogue
            const float* bc = g_bc;
#pragma unroll
            for (int mt = 0; mt < 4; mt++) {
#pragma unroll
                for (int pp = 0; pp < 2; pp++) {
                    int row = mt * 16 + g8 + pp * 8;
                    int ib  = mt * 16 + pp * 2;
                    float vi0 = acc[ib + 0]  + bc[col0],       vi1 = acc[ib + 1]  + bc[col1];
                    float vf0 = acc[ib + 4]  + bc[128 + col0], vf1 = acc[ib + 5]  + bc[128 + col1];
                    float vg0 = acc[ib + 8]  + bc[256 + col0], vg1 = acc[ib + 9]  + bc[256 + col1];
                    float vo0 = acc[ib + 12] + bc[384 + col0], vo1 = acc[ib + 13] + bc[384 + col1];
                    float cp0 = Ht[row * 132 + col0], cp1 = Ht[row * 132 + col1];
                    float cv0 = fsig(vf0) * cp0 + fsig(vi0) * ftanh(vg0);
                    float cv1 = fsig(vf1) * cp1 + fsig(vi1) * ftanh(vg1);
                    float hv0 = fsig(vo0) * ftanh(cv0);
                    float hv1 = fsig(vo1) * ftanh(cv1);
                    size_t gi = (size_t)(base + row) * 128 + col0;
                    *(float2*)(out_h1 + gi) = make_float2(hv0, hv1);
                    *(float2*)(out_c1 + gi) = make_float2(cv0, cv1);
                    float nx0 = (col0 >= 118) ? gmrow[col0 - 118] : hv0;
                    float nx1 = (col1 >= 118) ? gmrow[col1 - 118] : hv1;
                    *(float2*)(Xt + row * 132 + col0) = make_float2(tf32v(nx0), tf32v(nx1));
                }
            }
#pragma unroll
            for (int i = 0; i < 64; i++) acc[i] = 0.f;
            __syncthreads();
        }

        // ---- mma for chunk c
        const int kl = (c & 15) * 16;
        const float* wb = Wst + buf * WBUF;
#pragma unroll
        for (int ks = 0; ks < 2; ks++) {
            int kg = kl + ks * 8;
            const float* At_ = (kg < 128) ? (Xt + kg) : (Ht + (kg - 128));
            uint32_t afr[4][4];
#pragma unroll
            for (int mt = 0; mt < 4; mt++) {
                int r0 = mt * 16 + g8;
                afr[mt][0] = ldb(&At_[r0 * 132 + cc]);
                afr[mt][1] = ldb(&At_[(r0 + 8) * 132 + cc]);
                afr[mt][2] = ldb(&At_[r0 * 132 + cc + 4]);
                afr[mt][3] = ldb(&At_[(r0 + 8) * 132 + cc + 4]);
            }
#pragma unroll
            for (int q = 0; q < 4; q++) {
                int ncol = q * 128 + j0 + g8;
                uint32_t b0 = ldb(&wb[(ks * 8 + cc) * 520 + ncol]);
                uint32_t b1 = ldb(&wb[(ks * 8 + cc + 4) * 520 + ncol]);
#pragma unroll
                for (int mt = 0; mt < 4; mt++)
                    mma8(acc + mt * 16 + q * 4, afr[mt], b0, b1);
            }
        }
        __syncthreads();

        // ---- prefetch chunk c+2 (or decoder chunk) into buf
        if (c < 30) {
#pragma unroll
            for (int ii = 0; ii < 4; ii++) {
                int bpos = (ii * 512 + t) * 4;
                int kk = bpos >> 9, n = bpos & 511;
                cp16(wst_u + (uint32_t)(buf * WBUF + kk * 520 + n) * 4,
                     g_Wl + (size_t)((c + 2) * 16 + kk) * 512 + n);
            }
        } else {
            int dchunk = c - 30;   // 0 or 1
            if (t < 256) {
                int bpos = t * 4;
                int kk = bpos >> 6, n = bpos & 63;
                cp16(wst_u + (uint32_t)(buf * WBUF + kk * 72 + n) * 4,
                     g_Wd1_t + dchunk * 1024 + kk * 64 + n);
            }
        }
        CP_COMMIT();
    }

    // ---- cell1 epilogue: h2 -> Xt, c2 -> Ht
    {
        const float* bc = g_bc + 512;
#pragma unroll
        for (int mt = 0; mt < 4; mt++) {
#pragma unroll
            for (int pp = 0; pp < 2; pp++) {
                int row = mt * 16 + g8 + pp * 8;
                int ib  = mt * 16 + pp * 2;
                float vi0 = acc[ib + 0]  + bc[col0],       vi1 = acc[ib + 1]  + bc[col1];
                float vf0 = acc[ib + 4]  + bc[128 + col0], vf1 = acc[ib + 5]  + bc[128 + col1];
                float vg0 = acc[ib + 8]  + bc[256 + col0], vg1 = acc[ib + 9]  + bc[256 + col1];
                float vo0 = acc[ib + 12] + bc[384 + col0], vo1 = acc[ib + 13] + bc[384 + col1];
                float cp0 = Ht[row * 132 + col0], cp1 = Ht[row * 132 + col1];
                float cv0 = fsig(vf0) * cp0 + fsig(vi0) * ftanh(vg0);
                float cv1 = fsig(vf1) * cp1 + fsig(vi1) * ftanh(vg1);
                float hv0 = fsig(vo0) * ftanh(cv0);
                float hv1 = fsig(vo1) * ftanh(cv1);
                size_t gi = (size_t)(base + row) * 128 + col0;
                *(float2*)(out_h2 + gi) = make_float2(hv0, hv1);
                *(float2*)(out_c2 + gi) = make_float2(cv0, cv1);
                *(float2*)(Xt + row * 132 + col0) = make_float2(tf32v(hv0), tf32v(hv1));
                *(float2*)(Ht + row * 132 + col0) = make_float2(tf32v(cv0), tf32v(cv1));
            }
        }
    }
    __syncthreads();

    // ================= decoder: d1 = relu([h2|c2] @ Wd1 + b) =================
    {
        const int n0  = (w & 7) * 8;
        const int mt0 = (w >> 3) * 2;
        float accd[8];
#pragma unroll
        for (int i = 0; i < 8; i++) accd[i] = 0.f;

#pragma unroll 1
        for (int d = 0; d < 16; d++) {
            const int buf = d & 1;
            CP_WAIT(1);
            __syncthreads();
            const float* wb = Wst + buf * WBUF;
#pragma unroll
            for (int ks = 0; ks < 2; ks++) {
                int kg = d * 16 + ks * 8;
                const float* At_ = (kg < 128) ? (Xt + kg) : (Ht + (kg - 128));
                uint32_t b0 = ldb(&wb[(ks * 8 + cc) * 72 + n0 + g8]);
                uint32_t b1 = ldb(&wb[(ks * 8 + cc + 4) * 72 + n0 + g8]);
#pragma unroll
                for (int m = 0; m < 2; m++) {
                    int r0 = (mt0 + m) * 16 + g8;
                    uint32_t a[4];
                    a[0] = ldb(&At_[r0 * 132 + cc]);
                    a[1] = ldb(&At_[(r0 + 8) * 132 + cc]);
                    a[2] = ldb(&At_[r0 * 132 + cc + 4]);
                    a[3] = ldb(&At_[(r0 + 8) * 132 + cc + 4]);
                    mma8(accd + m * 4, a, b0, b1);
                }
            }
            __syncthreads();
            if (d < 14) {
                if (t < 256) {
                    int bpos = t * 4;
                    int kk = bpos >> 6, n = bpos & 63;
                    cp16(wst_u + (uint32_t)(buf * WBUF + kk * 72 + n) * 4,
                         g_Wd1_t + (d + 2) * 1024 + kk * 64 + n);
                }
            }
            CP_COMMIT();
        }
        int c0 = n0 + 2 * cc, c1 = c0 + 1;
        float b0 = bd1[c0], b1 = bd1[c1];
#pragma unroll
        for (int m = 0; m < 2; m++) {
#pragma unroll
            for (int pp = 0; pp < 2; pp++) {
                int row = (mt0 + m) * 16 + g8 + pp * 8;
                float v0 = fmaxf(accd[m * 4 + pp * 2]     + b0, 0.f);
                float v1 = fmaxf(accd[m * 4 + pp * 2 + 1] + b1, 0.f);
                *(float2*)(nct + row * 68 + c0) = make_float2(v0, v1);
            }
        }
    }
    __syncthreads();

    // ================= y = d1 @ Wd2 + b =================
    if (t < 384) {
        int r = t / 6, c = t - r * 6;
        float accy = bd2[c];
#pragma unroll
        for (int k = 0; k < 64; k++) accy = fmaf(nct[r * 68 + k], Wd2[k * 6 + c], accy);
        out_y[(size_t)(base + r) * 6 + c] = accy;
    }
}

// ----------------------------------------------------------------
extern "C" void kernel_launch(void* const* d_in, const int* in_sizes, int n_in,
                              void* d_out, int out_size)
{
    const float* x    = (const float*)d_in[0];
    const int*   ei   = (const int*)d_in[1];
    const float* ea   = (const float*)d_in[2];
    const int*   si   = (const int*)d_in[3];
    const float* gm   = (const float*)d_in[4];
    const float* Wm   = (const float*)d_in[5];
    const float* bm   = (const float*)d_in[6];
    const float* Wn   = (const float*)d_in[7];
    const float* bn   = (const float*)d_in[8];
    const float* We   = (const float*)d_in[9];
    const float* be_  = (const float*)d_in[10];
    const float* Wih0 = (const float*)d_in[11];
    const float* Whh0 = (const float*)d_in[12];
    const float* bih0 = (const float*)d_in[13];
    const float* bhh0 = (const float*)d_in[14];
    const float* Wih1 = (const float*)d_in[15];
    const float* Whh1 = (const float*)d_in[16];
    const float* bih1 = (const float*)d_in[17];
    const float* bhh1 = (const float*)d_in[18];
    const float* Wd1  = (const float*)d_in[19];
    const float* bd1  = (const float*)d_in[20];
    const float* Wd2  = (const float*)d_in[21];
    const float* bd2  = (const float*)d_in[22];
    float* out = (float*)d_out;

    const int smem_bytes = SMEM_F * 4;   // 200192
    cudaFuncSetAttribute(sample_kernel,
                         cudaFuncAttributeMaxDynamicSharedMemorySize, smem_bytes);

    prep_kernel<<<1189, 256>>>(Wih0, Whh0, Wih1, Whh1, We, Wd1, bih0, bhh0, bih1, bhh1);
    flag_zero_kernel<<<NS / 8, 256>>>(si);
    compact_edges_kernel<<<NE / 256, 256>>>(ei);
    compact_nodes_kernel<<<NN / 256, 256>>>();
    pre_kernel<<<2 * NN / 256, 256>>>(x, Wm, bm);
    edge_kernel<<<1024, 256>>>(ea, Wm);
    node_kernel<<<NS / 256, 256>>>(x, Wn, bn);
    sample_kernel<<<NS / 64, 512, smem_bytes>>>(
        si, gm, be_, bd1, Wd2, bd2, out);
}

// round 8
// speedup vs baseline: 1.1517x; 1.0034x over previous
#include <cuda_runtime.h>
#include <math.h>
#include <stdint.h>

#define NN (64*4096)      // 262144 nodes
#define NE (64*16384)     // 1048576 edges
#define NS (64*1024)      // 65536 sampled rows
#define IN_F 26

typedef unsigned long long ull;

// scratch (device globals)
__device__ __align__(16) float g_agg[(size_t)NN * 64];
__device__ __align__(16) float g_conv[(size_t)NN * 64];
__device__ __align__(16) float g_P[(size_t)NN * 128];
__device__ unsigned g_flagbits[NN / 32];
__device__ unsigned g_needsrc[NN / 32];
__device__ unsigned g_needdst[NN / 32];
__device__ int4  g_sde[NE];
__device__ int   g_nlist[NN];
__device__ int   g_plist[2 * NN];    // jobs: node*2 + half
__device__ int   g_cnt[4];
// pre-converted tf32 weights
__device__ __align__(16) float g_Wl[512 * 512];   // [cell0 Wih|Whh ; cell1 Wih|Whh]
__device__ __align__(16) float g_We_t[64 * 128];
__device__ __align__(16) float g_Wd1_t[256 * 64];
__device__ __align__(16) float g_bc[2 * 512];

// ---------------- packed f32x2 helpers ----------------
__device__ __forceinline__ ull pk(float lo, float hi) {
    ull r; asm("mov.b64 %0, {%1, %2};" : "=l"(r) : "f"(lo), "f"(hi)); return r;
}
__device__ __forceinline__ ull pk2(float v) { return pk(v, v); }
__device__ __forceinline__ float2 upk(ull v) {
    float2 r; asm("mov.b64 {%0, %1}, %2;" : "=f"(r.x), "=f"(r.y) : "l"(v)); return r;
}
__device__ __forceinline__ ull fma2(ull a, ull b, ull c) {
    ull d; asm("fma.rn.f32x2 %0, %1, %2, %3;" : "=l"(d) : "l"(a), "l"(b), "l"(c)); return d;
}
__device__ __forceinline__ ull add2(ull a, ull b) {
    ull d; asm("add.rn.f32x2 %0, %1, %2;" : "=l"(d) : "l"(a), "l"(b)); return d;
}
__device__ __forceinline__ float fsig(float x)  { return __fdividef(1.f, 1.f + __expf(-x)); }
__device__ __forceinline__ float ftanh(float x) { return 1.f - __fdividef(2.f, 1.f + __expf(2.f * x)); }

// ---------------- tf32 mma / cp.async helpers ----------------
__device__ __forceinline__ float tf32v(float f) {
    uint32_t r; asm("cvt.rna.tf32.f32 %0, %1;" : "=r"(r) : "f"(f));
    return __uint_as_float(r);
}
__device__ __forceinline__ void mma8(float* d, const uint32_t* a, uint32_t b0, uint32_t b1) {
    asm volatile(
        "mma.sync.aligned.m16n8k8.row.col.f32.tf32.tf32.f32 "
        "{%0,%1,%2,%3}, {%4,%5,%6,%7}, {%8,%9}, {%0,%1,%2,%3};"
        : "+f"(d[0]), "+f"(d[1]), "+f"(d[2]), "+f"(d[3])
        : "r"(a[0]), "r"(a[1]), "r"(a[2]), "r"(a[3]), "r"(b0), "r"(b1));
}
__device__ __forceinline__ uint32_t ldb(const float* p) { return __float_as_uint(*p); }
__device__ __forceinline__ void cp16(uint32_t dst, const float* src) {
    asm volatile("cp.async.cg.shared.global [%0], [%1], 16;" :: "r"(dst), "l"(src));
}
#define CP_COMMIT() asm volatile("cp.async.commit_group;")
#define CP_WAIT(n)  asm volatile("cp.async.wait_group " #n ";")
__device__ __forceinline__ void redv2(float* p, float a, float b) {
    asm volatile("red.global.add.v2.f32 [%0], {%1, %2};" :: "l"(p), "f"(a), "f"(b) : "memory");
}

// ---------------------------------------------------------------- prep: tf32 weights + zero tables
__global__ __launch_bounds__(256) void prep_kernel(
    const float* __restrict__ Wih0, const float* __restrict__ Whh0,
    const float* __restrict__ Wih1, const float* __restrict__ Whh1,
    const float* __restrict__ We,   const float* __restrict__ Wd1,
    const float* __restrict__ bih0, const float* __restrict__ bhh0,
    const float* __restrict__ bih1, const float* __restrict__ bhh1)
{
    int i = blockIdx.x * 256 + threadIdx.x;
    if (i < 262144) {
        int cell = i >> 17, r = (i >> 9) & 255, n = i & 511;
        const float* W = (r < 128) ? (cell ? Wih1 : Wih0) : (cell ? Whh1 : Whh0);
        g_Wl[i] = tf32v(W[(r & 127) * 512 + n]);
    } else if (i < 270336) {
        int j = i - 262144; g_We_t[j] = tf32v(We[j]);
    } else if (i < 286720) {
        int j = i - 270336; g_Wd1_t[j] = tf32v(Wd1[j]);
    } else if (i < 287744) {
        int j = i - 286720; int cell = j >> 9; int n = j & 511;
        g_bc[j] = cell ? (bih1[n] + bhh1[n]) : (bih0[n] + bhh0[n]);
    } else if (i < 295936) {
        g_flagbits[i - 287744] = 0u;
    } else if (i < 304128) {
        g_needsrc[i - 295936] = 0u;
    } else if (i < 312320) {
        g_needdst[i - 304128] = 0u;
    } else if (i < 312324) {
        g_cnt[i - 312320] = 0;
    }
}

// ---------------------------------------------------------------- flag + zero agg rows (warp/sample)
__global__ __launch_bounds__(256) void flag_zero_kernel(const int* __restrict__ si) {
    int gw = blockIdx.x * 8 + (threadIdx.x >> 5);
    int l  = threadIdx.x & 31;
    int n  = si[gw];
    if (l == 0) atomicOr(&g_flagbits[n >> 5], 1u << (n & 31));
    ((float2*)(g_agg + (size_t)n * 64))[l] = make_float2(0.f, 0.f);
}

// ---------------------------------------------------------------- edge compaction (bit flags)
__global__ __launch_bounds__(256) void compact_edges_kernel(const int* __restrict__ ei) {
    int e = blockIdx.x * 256 + threadIdx.x;
    int d = ei[NE + e];
    bool act = (g_flagbits[d >> 5] >> (d & 31)) & 1u;
    unsigned m = __ballot_sync(0xffffffffu, act);
    if (m) {
        int lane = threadIdx.x & 31;
        int leader = __ffs(m) - 1;
        int pos = 0;
        if (lane == leader) pos = atomicAdd(&g_cnt[0], __popc(m));
        pos = __shfl_sync(0xffffffffu, pos, leader);
        pos += __popc(m & ((1u << lane) - 1));
        if (act) {
            int s = ei[e];
            g_sde[pos] = make_int4(s, d, e, 0);
            atomicOr(&g_needsrc[s >> 5], 1u << (s & 31));
            atomicOr(&g_needdst[d >> 5], 1u << (d & 31));
        }
    }
}

// ---------------------------------------------------------------- node compaction + P-job list
__global__ __launch_bounds__(256) void compact_nodes_kernel() {
    int n = blockIdx.x * 256 + threadIdx.x;
    int lane = threadIdx.x & 31;
    {
        bool a = (g_flagbits[n >> 5] >> (n & 31)) & 1u;
        unsigned m = __ballot_sync(0xffffffffu, a);
        if (m) {
            int leader = __ffs(m) - 1;
            int pos = 0;
            if (lane == leader) pos = atomicAdd(&g_cnt[1], __popc(m));
            pos = __shfl_sync(0xffffffffu, pos, leader);
            pos += __popc(m & ((1u << lane) - 1));
            if (a) g_nlist[pos] = n;
        }
    }
    {
        bool a = (g_needsrc[n >> 5] >> (n & 31)) & 1u;
        unsigned m = __ballot_sync(0xffffffffu, a);
        if (m) {
            int leader = __ffs(m) - 1;
            int pos = 0;
            if (lane == leader) pos = atomicAdd(&g_cnt[2], __popc(m));
            pos = __shfl_sync(0xffffffffu, pos, leader);
            pos += __popc(m & ((1u << lane) - 1));
            if (a) g_plist[pos] = 2 * n;
        }
    }
    {
        bool a = (g_needdst[n >> 5] >> (n & 31)) & 1u;
        unsigned m = __ballot_sync(0xffffffffu, a);
        if (m) {
            int leader = __ffs(m) - 1;
            int pos = 0;
            if (lane == leader) pos = atomicAdd(&g_cnt[2], __popc(m));
            pos = __shfl_sync(0xffffffffu, pos, leader);
            pos += __popc(m & ((1u << lane) - 1));
            if (a) g_plist[pos] = 2 * n + 1;
        }
    }
}

// ---------------------------------------------------------------- per-node edge precompute (job list)
__global__ __launch_bounds__(256) void pre_kernel(
    const float* __restrict__ x, const float* __restrict__ Wm,
    const float* __restrict__ bm)
{
    __shared__ float Ws[52 * 64];
    __shared__ float bs[64];
    for (int i = threadIdx.x; i < 52 * 64; i += 256) Ws[i] = Wm[i];
    if (threadIdx.x < 64) bs[threadIdx.x] = bm[threadIdx.x];
    __syncthreads();

    int i = blockIdx.x * 256 + threadIdx.x;
    if (i >= g_cnt[2]) return;
    int job  = g_plist[i];
    int n    = job >> 1;
    int half = job & 1;

    ull acc[32];
#pragma unroll
    for (int j = 0; j < 32; j++)
        acc[j] = half ? 0ull : pk(bs[2 * j], bs[2 * j + 1]);

    const float2* xr = (const float2*)(x + (size_t)n * IN_F);
    const int rbase = half * IN_F;
#pragma unroll
    for (int kk = 0; kk < 13; kk++) {
        float2 xv = xr[kk];
#pragma unroll
        for (int h = 0; h < 2; h++) {
            ull v = pk2(h ? xv.y : xv.x);
            const ulonglong2* wr = (const ulonglong2*)&Ws[(rbase + 2 * kk + h) * 64];
#pragma unroll
            for (int j = 0; j < 16; j++) {
                ulonglong2 w = wr[j];
                acc[2 * j]     = fma2(v, w.x, acc[2 * j]);
                acc[2 * j + 1] = fma2(v, w.y, acc[2 * j + 1]);
            }
        }
    }
    float4* dst = (float4*)(g_P + (size_t)n * 128 + half * 64);
#pragma unroll
    for (int j = 0; j < 16; j++) {
        float2 a = upk(acc[2 * j]), b = upk(acc[2 * j + 1]);
        dst[j] = make_float4(a.x, a.y, b.x, b.y);
    }
}

// ---------------------------------------------------------------- edges (active only, red.v2)
__global__ __launch_bounds__(256) void edge_kernel(const float* __restrict__ ea,
                                                   const float* __restrict__ Wm)
{
    __shared__ float Ws[15 * 64];
    for (int i = threadIdx.x; i < 15 * 64; i += 256) Ws[i] = Wm[52 * 64 + i];
    __syncthreads();

    const int l  = threadIdx.x & 31;
    const int gw = blockIdx.x * 8 + (threadIdx.x >> 5);
    const int W  = gridDim.x * 8;
    const int ec = g_cnt[0];

    for (int i = gw; i < ec; i += W) {
        int4 sde = g_sde[i];
        ull ps = *(const ull*)(g_P + (size_t)sde.x * 128 + 2 * l);
        ull pd = *(const ull*)(g_P + (size_t)sde.y * 128 + 64 + 2 * l);
        ull acc = add2(ps, pd);
        const float* er = ea + (size_t)sde.z * 15;
#pragma unroll
        for (int k = 0; k < 15; k++) {
            ull w = *(const ull*)&Ws[k * 64 + 2 * l];
            acc = fma2(pk2(er[k]), w, acc);
        }
        float2 a = upk(acc);
        redv2(g_agg + (size_t)sde.y * 64 + 2 * l, fmaxf(a.x, 0.f), fmaxf(a.y, 0.f));
    }
}

// ---------------------------------------------------------------- nodes (sampled only)
__global__ __launch_bounds__(256) void node_kernel(
    const float* __restrict__ x, const float* __restrict__ Wn,
    const float* __restrict__ bn)
{
    __shared__ float Ws[90 * 64];
    __shared__ float bs[64];
    for (int i = threadIdx.x; i < 90 * 64; i += 256) Ws[i] = Wn[i];
    if (threadIdx.x < 64) bs[threadIdx.x] = bn[threadIdx.x];
    __syncthreads();

    int i = blockIdx.x * 256 + threadIdx.x;
    if (i >= g_cnt[1]) return;
    int n = g_nlist[i];

    ull acc[32];
#pragma unroll
    for (int j = 0; j < 32; j++) acc[j] = pk(bs[2 * j], bs[2 * j + 1]);

    const float2* xr = (const float2*)(x + (size_t)n * IN_F);
#pragma unroll
    for (int kk = 0; kk < 13; kk++) {
        float2 xv = xr[kk];
#pragma unroll
        for (int h = 0; h < 2; h++) {
            ull v = pk2(h ? xv.y : xv.x);
            const ulonglong2* wr = (const ulonglong2*)&Ws[(2 * kk + h) * 64];
#pragma unroll
            for (int j = 0; j < 16; j++) {
                ulonglong2 w = wr[j];
                acc[2 * j]     = fma2(v, w.x, acc[2 * j]);
                acc[2 * j + 1] = fma2(v, w.y, acc[2 * j + 1]);
            }
        }
    }
    const float4* ar = (const float4*)(g_agg + (size_t)n * 64);
#pragma unroll
    for (int kk = 0; kk < 16; kk++) {
        float4 av = ar[kk];
#pragma unroll
        for (int h = 0; h < 4; h++) {
            float vf = h == 0 ? av.x : h == 1 ? av.y : h == 2 ? av.z : av.w;
            ull v = pk2(vf);
            const ulonglong2* wr = (const ulonglong2*)&Ws[(IN_F + 4 * kk + h) * 64];
#pragma unroll
            for (int j = 0; j < 16; j++) {
                ulonglong2 w = wr[j];
                acc[2 * j]     = fma2(v, w.x, acc[2 * j]);
                acc[2 * j + 1] = fma2(v, w.y, acc[2 * j + 1]);
            }
        }
    }
    float4* dst = (float4*)(g_conv + (size_t)n * 64);
#pragma unroll
    for (int j = 0; j < 16; j++) {
        float2 a = upk(acc[2 * j]), b = upk(acc[2 * j + 1]);
        dst[j] = make_float4(fmaxf(a.x, 0.f), fmaxf(a.y, 0.f),
                             fmaxf(b.x, 0.f), fmaxf(b.y, 0.f));
    }
}

// ---------------------------------------------------------------- fused sampled pipeline
// 64 rows/CTA, 512 threads. Triple-buffered ring, specialized loops, 1 sync/chunk.
// chunk map: 0-3 encoder, 4-19 cell0, 20-35 cell1, 36-51 decoder.
#define O_NCT 0            // [64][68]
#define O_A2  4352         // [64][20]
#define O_XT  5632         // [64][132]
#define O_HT  14080        // [64][132]
#define O_WST 22528        // 3 x [16][520]
#define WBUF  8320
#define SMEM_F 47488       // 189952 bytes

__global__ __launch_bounds__(512, 1) void sample_kernel(
    const int* __restrict__ sidx_g, const float* __restrict__ gm,
    const float* __restrict__ be,
    const float* __restrict__ bd1,
    const float* __restrict__ Wd2, const float* __restrict__ bd2,
    float* __restrict__ out)
{
    extern __shared__ float sm[];
    float* nct = sm + O_NCT;
    float* A2  = sm + O_A2;
    float* Xt  = sm + O_XT;
    float* Ht  = sm + O_HT;
    float* Wst = sm + O_WST;
    __shared__ float gmrow[10];
    __shared__ int   sidx[64];

    const int t    = threadIdx.x;
    const int base = blockIdx.x * 64;
    const uint32_t wst_u = (uint32_t)__cvta_generic_to_shared(Wst);

    if (t < 64) sidx[t] = sidx_g[base + t];
    if (t < 10) gmrow[t] = gm[(blockIdx.x >> 4) * 10 + t];

    // prefetch chunk c2 -> ring buffer c2%3 (one commit group per call)
    auto prefetch = [&](int c2) {
        uint32_t db = wst_u + (uint32_t)((c2 % 3) * WBUF) * 4;
        if (c2 < 4) {
            int bpos = t * 4; int kk = bpos >> 7, n = bpos & 127;
            cp16(db + (uint32_t)(kk * 520 + n) * 4, g_We_t + c2 * 2048 + kk * 128 + n);
        } else if (c2 < 36) {
#pragma unroll
            for (int ii = 0; ii < 4; ii++) {
                int bpos = (ii * 512 + t) * 4; int kk = bpos >> 9, n = bpos & 511;
                cp16(db + (uint32_t)(kk * 520 + n) * 4,
                     g_Wl + (size_t)(c2 - 4) * 8192 + kk * 512 + n);
            }
        } else if (c2 < 52) {
            if (t < 256) {
                int bpos = t * 4; int kk = bpos >> 6, n = bpos & 63;
                cp16(db + (uint32_t)(kk * 520 + n) * 4,
                     g_Wd1_t + (c2 - 36) * 1024 + kk * 64 + n);
            }
        }
        CP_COMMIT();
    };
    prefetch(0);
    prefetch(1);

    __syncthreads();   // sidx visible

    float* out_nc = out;
    float* out_h1 = out + (size_t)NS * 64;
    float* out_c1 = out_h1 + (size_t)NS * 128;
    float* out_h2 = out_c1 + (size_t)NS * 128;
    float* out_c2 = out_h2 + (size_t)NS * 128;
    float* out_y  = out_c2 + (size_t)NS * 128;

    // gather node_conv (tf32) + out_nc (exact) + A2 (rows 10..15 zero)
    for (int idx = t; idx < 64 * 64; idx += 512) {
        int r = idx >> 6, c = idx & 63;
        float v = g_conv[(size_t)sidx[r] * 64 + c];
        nct[r * 68 + c] = tf32v(v);
        out_nc[(size_t)(base + r) * 64 + c] = v;
    }
    for (int idx = t; idx < 64 * 20; idx += 512) {
        int r = idx / 20, kk = idx - r * 20;
        A2[idx] = (kk < 10) ? tf32v(g_conv[(size_t)sidx[r] * 64 + 54 + kk]) : 0.f;
    }
    __syncthreads();   // nct/A2 visible before encoder mma

    const int w    = t >> 5;
    const int lane = t & 31;
    const int g8   = lane >> 2;
    const int cc   = lane & 3;
    const int j0   = w * 8;
    const int col0 = j0 + 2 * cc, col1 = col0 + 1;

    float acc[64];
#pragma unroll
    for (int i = 0; i < 64; i++) acc[i] = 0.f;

    // ================= encoder: chunks 0..3 =================
#pragma unroll 1
    for (int c = 0; c < 4; c++) {
        CP_WAIT(1);
        __syncthreads();
        prefetch(c + 2);
        const float* wb = Wst + (c % 3) * WBUF;
#pragma unroll
        for (int ks = 0; ks < 2; ks++) {
            int k0 = c * 16 + ks * 8;
            uint32_t b0 = ldb(&wb[(ks * 8 + cc) * 520 + j0 + g8]);
            uint32_t b1 = ldb(&wb[(ks * 8 + cc + 4) * 520 + j0 + g8]);
#pragma unroll
            for (int mt = 0; mt < 4; mt++) {
                int r0 = mt * 16 + g8;
                uint32_t a[4];
                a[0] = ldb(&nct[r0 * 68 + k0 + cc]);
                a[1] = ldb(&nct[(r0 + 8) * 68 + k0 + cc]);
                a[2] = ldb(&nct[r0 * 68 + k0 + cc + 4]);
                a[3] = ldb(&nct[(r0 + 8) * 68 + k0 + cc + 4]);
                mma8(acc + mt * 4, a, b0, b1);
            }
        }
    }

    // ---- gm-correction mma: B = We rows 54..63 = ring chunk-3 buffer rows 6..15
    {
        const float* wb = Wst + (3 % 3) * WBUF;   // buffer 0 holds chunk 3
#pragma unroll
        for (int ks = 0; ks < 2; ks++) {
            int k0 = ks * 8;
            uint32_t b0 = ldb(&wb[(6 + k0 + cc) * 520 + j0 + g8]);
            uint32_t b1 = ldb(&wb[(6 + k0 + cc + 4) * 520 + j0 + g8]);
#pragma unroll
            for (int mt = 0; mt < 4; mt++) {
                int r0 = mt * 16 + g8;
                uint32_t a[4];
                a[0] = ldb(&A2[r0 * 20 + k0 + cc]);
                a[1] = ldb(&A2[(r0 + 8) * 20 + k0 + cc]);
                a[2] = ldb(&A2[r0 * 20 + k0 + cc + 4]);
                a[3] = ldb(&A2[(r0 + 8) * 20 + k0 + cc + 4]);
                mma8(acc + 16 + mt * 4, a, b0, b1);
            }
        }
        // encoder epilogue
        float be0 = be[col0], be1 = be[col1];
        float gs0 = 0.f, gs1 = 0.f;
#pragma unroll
        for (int k = 0; k < 10; k++) {
            gs0 = fmaf(gmrow[k], wb[(6 + k) * 520 + col0], gs0);
            gs1 = fmaf(gmrow[k], wb[(6 + k) * 520 + col1], gs1);
        }
#pragma unroll
        for (int mt = 0; mt < 4; mt++) {
#pragma unroll
            for (int pp = 0; pp < 2; pp++) {
                int row = mt * 16 + g8 + pp * 8;
                float hp0 = acc[mt * 4 + pp * 2],      hp1 = acc[mt * 4 + pp * 2 + 1];
                float cr0 = acc[16 + mt * 4 + pp * 2], cr1 = acc[16 + mt * 4 + pp * 2 + 1];
                *(float2*)(Xt + row * 132 + col0) =
                    make_float2(tf32v(fmaxf(hp0 - cr0 + gs0 + be0, 0.f)),
                                tf32v(fmaxf(hp1 - cr1 + gs1 + be1, 0.f)));
                *(float2*)(Ht + row * 132 + col0) =
                    make_float2(tf32v(fmaxf(hp0 + be0, 0.f)),
                                tf32v(fmaxf(hp1 + be1, 0.f)));
            }
        }
#pragma unroll
        for (int i = 0; i < 64; i++) acc[i] = 0.f;
    }
    __syncthreads();   // Xt/Ht visible before cell0 mma

    // ================= LSTM cells: chunks 4..35 =================
#pragma unroll 1
    for (int cell = 0; cell < 2; cell++) {
        const int cbase = 4 + cell * 16;
#pragma unroll 1
        for (int cl = 0; cl < 16; cl++) {
            const int c = cbase + cl;
            CP_WAIT(1);
            __syncthreads();
            prefetch(c + 2);
            const int kl = cl * 16;
            const float* wb = Wst + (c % 3) * WBUF;
#pragma unroll
            for (int ks = 0; ks < 2; ks++) {
                int kg = kl + ks * 8;
                const float* At_ = (kg < 128) ? (Xt + kg) : (Ht + (kg - 128));
                uint32_t afr[4][4];
#pragma unroll
                for (int mt = 0; mt < 4; mt++) {
                    int r0 = mt * 16 + g8;
                    afr[mt][0] = ldb(&At_[r0 * 132 + cc]);
                    afr[mt][1] = ldb(&At_[(r0 + 8) * 132 + cc]);
                    afr[mt][2] = ldb(&At_[r0 * 132 + cc + 4]);
                    afr[mt][3] = ldb(&At_[(r0 + 8) * 132 + cc + 4]);
                }
#pragma unroll
                for (int q = 0; q < 4; q++) {
                    int ncol = q * 128 + j0 + g8;
                    uint32_t b0 = ldb(&wb[(ks * 8 + cc) * 520 + ncol]);
                    uint32_t b1 = ldb(&wb[(ks * 8 + cc + 4) * 520 + ncol]);
#pragma unroll
                    for (int mt = 0; mt < 4; mt++)
                        mma8(acc + mt * 16 + q * 4, afr[mt], b0, b1);
                }
            }
        }

        // ---- cell epilogue (needs all warps past their last mma read of Xt/Ht)
        __syncthreads();
        {
            const float* bc = g_bc + cell * 512;
            float* oH = cell ? out_h2 : out_h1;
            float* oC = cell ? out_c2 : out_c1;
#pragma unroll
            for (int mt = 0; mt < 4; mt++) {
#pragma unroll
                for (int pp = 0; pp < 2; pp++) {
                    int row = mt * 16 + g8 + pp * 8;
                    int ib  = mt * 16 + pp * 2;
                    float vi0 = acc[ib + 0]  + bc[col0],       vi1 = acc[ib + 1]  + bc[col1];
                    float vf0 = acc[ib + 4]  + bc[128 + col0], vf1 = acc[ib + 5]  + bc[128 + col1];
                    float vg0 = acc[ib + 8]  + bc[256 + col0], vg1 = acc[ib + 9]  + bc[256 + col1];
                    float vo0 = acc[ib + 12] + bc[384 + col0], vo1 = acc[ib + 13] + bc[384 + col1];
                    float cp0 = Ht[row * 132 + col0], cp1 = Ht[row * 132 + col1];
                    float cv0 = fsig(vf0) * cp0 + fsig(vi0) * ftanh(vg0);
                    float cv1 = fsig(vf1) * cp1 + fsig(vi1) * ftanh(vg1);
                    float hv0 = fsig(vo0) * ftanh(cv0);
                    float hv1 = fsig(vo1) * ftanh(cv1);
                    size_t gi = (size_t)(base + row) * 128 + col0;
                    *(float2*)(oH + gi) = make_float2(hv0, hv1);
                    *(float2*)(oC + gi) = make_float2(cv0, cv1);
                    if (cell == 0) {
                        float nx0 = (col0 >= 118) ? gmrow[col0 - 118] : hv0;
                        float nx1 = (col1 >= 118) ? gmrow[col1 - 118] : hv1;
                        *(float2*)(Xt + row * 132 + col0) = make_float2(tf32v(nx0), tf32v(nx1));
                    } else {
                        *(float2*)(Xt + row * 132 + col0) = make_float2(tf32v(hv0), tf32v(hv1));
                        *(float2*)(Ht + row * 132 + col0) = make_float2(tf32v(cv0), tf32v(cv1));
                    }
                }
            }
#pragma unroll
            for (int i = 0; i < 64; i++) acc[i] = 0.f;
        }
        __syncthreads();   // new Xt/Ht visible
    }

    // ================= decoder: chunks 36..51 =================
    {
        const int n0  = (w & 7) * 8;
        const int mt0 = (w >> 3) * 2;
#pragma unroll 1
        for (int dl = 0; dl < 16; dl++) {
            const int c = 36 + dl;
            CP_WAIT(1);
            __syncthreads();
            prefetch(c + 2);
            const float* wb = Wst + (c % 3) * WBUF;
#pragma unroll
            for (int ks = 0; ks < 2; ks++) {
                int kg = dl * 16 + ks * 8;
                const float* At_ = (kg < 128) ? (Xt + kg) : (Ht + (kg - 128));
                uint32_t b0 = ldb(&wb[(ks * 8 + cc) * 520 + n0 + g8]);
                uint32_t b1 = ldb(&wb[(ks * 8 + cc + 4) * 520 + n0 + g8]);
#pragma unroll
                for (int m = 0; m < 2; m++) {
                    int r0 = (mt0 + m) * 16 + g8;
                    uint32_t a[4];
                    a[0] = ldb(&At_[r0 * 132 + cc]);
                    a[1] = ldb(&At_[(r0 + 8) * 132 + cc]);
                    a[2] = ldb(&At_[r0 * 132 + cc + 4]);
                    a[3] = ldb(&At_[(r0 + 8) * 132 + cc + 4]);
                    mma8(acc + m * 4, a, b0, b1);
                }
            }
        }
        __syncthreads();   // all decoder reads of nct-region? (nct untouched) — protects d1 write below
        int c0 = n0 + 2 * cc, c1 = c0 + 1;
        float b0 = bd1[c0], b1 = bd1[c1];
#pragma unroll
        for (int m = 0; m < 2; m++) {
#pragma unroll
            for (int pp = 0; pp < 2; pp++) {
                int row = (mt0 + m) * 16 + g8 + pp * 8;
                float v0 = fmaxf(acc[m * 4 + pp * 2]     + b0, 0.f);
                float v1 = fmaxf(acc[m * 4 + pp * 2 + 1] + b1, 0.f);
                *(float2*)(nct + row * 68 + c0) = make_float2(v0, v1);
            }
        }
    }
    __syncthreads();

    // y = d1 @ Wd2 + b
    if (t < 384) {
        int r = t / 6, c = t - r * 6;
        float accy = bd2[c];
#pragma unroll
        for (int k = 0; k < 64; k++) accy = fmaf(nct[r * 68 + k], Wd2[k * 6 + c], accy);
        out_y[(size_t)(base + r) * 6 + c] = accy;
    }
}

// ----------------------------------------------------------------
extern "C" void kernel_launch(void* const* d_in, const int* in_sizes, int n_in,
                              void* d_out, int out_size)
{
    const float* x    = (const float*)d_in[0];
    const int*   ei   = (const int*)d_in[1];
    const float* ea   = (const float*)d_in[2];
    const int*   si   = (const int*)d_in[3];
    const float* gm   = (const float*)d_in[4];
    const float* Wm   = (const float*)d_in[5];
    const float* bm   = (const float*)d_in[6];
    const float* Wn   = (const float*)d_in[7];
    const float* bn   = (const float*)d_in[8];
    const float* We   = (const float*)d_in[9];
    const float* be_  = (const float*)d_in[10];
    const float* Wih0 = (const float*)d_in[11];
    const float* Whh0 = (const float*)d_in[12];
    const float* bih0 = (const float*)d_in[13];
    const float* bhh0 = (const float*)d_in[14];
    const float* Wih1 = (const float*)d_in[15];
    const float* Whh1 = (const float*)d_in[16];
    const float* bih1 = (const float*)d_in[17];
    const float* bhh1 = (const float*)d_in[18];
    const float* Wd1  = (const float*)d_in[19];
    const float* bd1  = (const float*)d_in[20];
    const float* Wd2  = (const float*)d_in[21];
    const float* bd2  = (const float*)d_in[22];
    float* out = (float*)d_out;

    const int smem_bytes = SMEM_F * 4;   // 189952
    cudaFuncSetAttribute(sample_kernel,
                         cudaFuncAttributeMaxDynamicSharedMemorySize, smem_bytes);

    prep_kernel<<<1221, 256>>>(Wih0, Whh0, Wih1, Whh1, We, Wd1, bih0, bhh0, bih1, bhh1);
    flag_zero_kernel<<<NS / 8, 256>>>(si);
    compact_edges_kernel<<<NE / 256, 256>>>(ei);
    compact_nodes_kernel<<<NN / 256, 256>>>();
    pre_kernel<<<2 * NN / 256, 256>>>(x, Wm, bm);
    edge_kernel<<<1024, 256>>>(ea, Wm);
    node_kernel<<<NS / 256, 256>>>(x, Wn, bn);
    sample_kernel<<<NS / 64, 512, smem_bytes>>>(
        si, gm, be_, bd1, Wd2, bd2, out);
}

// round 9
// speedup vs baseline: 1.1680x; 1.0141x over previous
#include <cuda_runtime.h>
#include <math.h>
#include <stdint.h>

#define NN (64*4096)      // 262144 nodes
#define NE (64*16384)     // 1048576 edges
#define NS (64*1024)      // 65536 sampled rows
#define NN2 (NN/2)
#define NE2 (NE/2)
#define NS2 (NS/2)
#define IN_F 26

typedef unsigned long long ull;

// scratch (device globals)
__device__ __align__(16) float g_agg[(size_t)NN * 64];
__device__ __align__(16) float g_conv[(size_t)NN * 64];
__device__ __align__(16) float g_P[(size_t)NN * 128];
__device__ unsigned g_flagbits[NN / 32];
__device__ unsigned g_needsrc[NN / 32];
__device__ unsigned g_needdst[NN / 32];
__device__ int4  g_sde[NE];
__device__ int   g_nlist[NN];
__device__ int   g_plist[2 * NN];    // jobs: node*2 + half-of-P
__device__ int   g_cnt[8];           // [h*4 + slot]
// pre-converted tf32 weights
__device__ __align__(16) float g_Wl[512 * 512];
__device__ __align__(16) float g_We_t[64 * 128];
__device__ __align__(16) float g_Wd1_t[256 * 64];
__device__ __align__(16) float g_bc[2 * 512];

// ---------------- packed f32x2 helpers ----------------
__device__ __forceinline__ ull pk(float lo, float hi) {
    ull r; asm("mov.b64 %0, {%1, %2};" : "=l"(r) : "f"(lo), "f"(hi)); return r;
}
__device__ __forceinline__ ull pk2(float v) { return pk(v, v); }
__device__ __forceinline__ float2 upk(ull v) {
    float2 r; asm("mov.b64 {%0, %1}, %2;" : "=f"(r.x), "=f"(r.y) : "l"(v)); return r;
}
__device__ __forceinline__ ull fma2(ull a, ull b, ull c) {
    ull d; asm("fma.rn.f32x2 %0, %1, %2, %3;" : "=l"(d) : "l"(a), "l"(b), "l"(c)); return d;
}
__device__ __forceinline__ ull add2(ull a, ull b) {
    ull d; asm("add.rn.f32x2 %0, %1, %2;" : "=l"(d) : "l"(a), "l"(b)); return d;
}
__device__ __forceinline__ float fsig(float x)  { return __fdividef(1.f, 1.f + __expf(-x)); }
__device__ __forceinline__ float ftanh(float x) { return 1.f - __fdividef(2.f, 1.f + __expf(2.f * x)); }

// ---------------- tf32 mma / cp.async helpers ----------------
__device__ __forceinline__ float tf32v(float f) {
    uint32_t r; asm("cvt.rna.tf32.f32 %0, %1;" : "=r"(r) : "f"(f));
    return __uint_as_float(r);
}
__device__ __forceinline__ void mma8(float* d, const uint32_t* a, uint32_t b0, uint32_t b1) {
    asm volatile(
        "mma.sync.aligned.m16n8k8.row.col.f32.tf32.tf32.f32 "
        "{%0,%1,%2,%3}, {%4,%5,%6,%7}, {%8,%9}, {%0,%1,%2,%3};"
        : "+f"(d[0]), "+f"(d[1]), "+f"(d[2]), "+f"(d[3])
        : "r"(a[0]), "r"(a[1]), "r"(a[2]), "r"(a[3]), "r"(b0), "r"(b1));
}
__device__ __forceinline__ uint32_t ldb(const float* p) { return __float_as_uint(*p); }
__device__ __forceinline__ void cp16(uint32_t dst, const float* src) {
    asm volatile("cp.async.cg.shared.global [%0], [%1], 16;" :: "r"(dst), "l"(src));
}
#define CP_COMMIT() asm volatile("cp.async.commit_group;")
#define CP_WAIT(n)  asm volatile("cp.async.wait_group " #n ";")
__device__ __forceinline__ void redv2(float* p, float a, float b) {
    asm volatile("red.global.add.v2.f32 [%0], {%1, %2};" :: "l"(p), "f"(a), "f"(b) : "memory");
}

// ---------------------------------------------------------------- prep: tf32 weight conversion only
__global__ __launch_bounds__(256) void prep_kernel(
    const float* __restrict__ Wih0, const float* __restrict__ Whh0,
    const float* __restrict__ Wih1, const float* __restrict__ Whh1,
    const float* __restrict__ We,   const float* __restrict__ Wd1,
    const float* __restrict__ bih0, const float* __restrict__ bhh0,
    const float* __restrict__ bih1, const float* __restrict__ bhh1)
{
    int i = blockIdx.x * 256 + threadIdx.x;
    if (i < 262144) {
        int cell = i >> 17, r = (i >> 9) & 255, n = i & 511;
        const float* W = (r < 128) ? (cell ? Wih1 : Wih0) : (cell ? Whh1 : Whh0);
        g_Wl[i] = tf32v(W[(r & 127) * 512 + n]);
    } else if (i < 270336) {
        int j = i - 262144; g_We_t[j] = tf32v(We[j]);
    } else if (i < 286720) {
        int j = i - 270336; g_Wd1_t[j] = tf32v(Wd1[j]);
    } else if (i < 287744) {
        int j = i - 286720; int cell = j >> 9; int n = j & 511;
        g_bc[j] = cell ? (bih1[n] + bhh1[n]) : (bih0[n] + bhh0[n]);
    }
}

// ---------------------------------------------------------------- per-half table zeroing
__global__ __launch_bounds__(256) void zero_tables_kernel(int h) {
    int i = blockIdx.x * 256 + threadIdx.x;
    int b = h * (NN2 / 32);
    if (i < 4096) g_flagbits[b + i] = 0u;
    else if (i < 8192) g_needsrc[b + i - 4096] = 0u;
    else if (i < 12288) g_needdst[b + i - 8192] = 0u;
    else if (i < 12292) g_cnt[h * 4 + i - 12288] = 0;
}

// ---------------------------------------------------------------- flag + zero agg rows (warp/sample)
__global__ __launch_bounds__(256) void flag_zero_kernel(const int* __restrict__ si, int h) {
    int gw = blockIdx.x * 8 + (threadIdx.x >> 5);
    int l  = threadIdx.x & 31;
    int n  = si[h * NS2 + gw];
    if (l == 0) atomicOr(&g_flagbits[n >> 5], 1u << (n & 31));
    ((float2*)(g_agg + (size_t)n * 64))[l] = make_float2(0.f, 0.f);
}

// ---------------------------------------------------------------- edge compaction (bit flags)
__global__ __launch_bounds__(256) void compact_edges_kernel(const int* __restrict__ ei, int h) {
    int e = h * NE2 + blockIdx.x * 256 + threadIdx.x;
    int d = ei[NE + e];
    bool act = (g_flagbits[d >> 5] >> (d & 31)) & 1u;
    unsigned m = __ballot_sync(0xffffffffu, act);
    if (m) {
        int lane = threadIdx.x & 31;
        int leader = __ffs(m) - 1;
        int pos = 0;
        if (lane == leader) pos = atomicAdd(&g_cnt[h * 4], __popc(m));
        pos = __shfl_sync(0xffffffffu, pos, leader);
        pos += __popc(m & ((1u << lane) - 1));
        if (act) {
            int s = ei[e];
            g_sde[h * NE2 + pos] = make_int4(s, d, e, 0);
            atomicOr(&g_needsrc[s >> 5], 1u << (s & 31));
            atomicOr(&g_needdst[d >> 5], 1u << (d & 31));
        }
    }
}

// ---------------------------------------------------------------- node compaction + P-job list
__global__ __launch_bounds__(256) void compact_nodes_kernel(int h) {
    int n = h * NN2 + blockIdx.x * 256 + threadIdx.x;
    int lane = threadIdx.x & 31;
    {
        bool a = (g_flagbits[n >> 5] >> (n & 31)) & 1u;
        unsigned m = __ballot_sync(0xffffffffu, a);
        if (m) {
            int leader = __ffs(m) - 1;
            int pos = 0;
            if (lane == leader) pos = atomicAdd(&g_cnt[h * 4 + 1], __popc(m));
            pos = __shfl_sync(0xffffffffu, pos, leader);
            pos += __popc(m & ((1u << lane) - 1));
            if (a) g_nlist[h * NN2 + pos] = n;
        }
    }
    {
        bool a = (g_needsrc[n >> 5] >> (n & 31)) & 1u;
        unsigned m = __ballot_sync(0xffffffffu, a);
        if (m) {
            int leader = __ffs(m) - 1;
            int pos = 0;
            if (lane == leader) pos = atomicAdd(&g_cnt[h * 4 + 2], __popc(m));
            pos = __shfl_sync(0xffffffffu, pos, leader);
            pos += __popc(m & ((1u << lane) - 1));
            if (a) g_plist[h * NN + pos] = 2 * n;
        }
    }
    {
        bool a = (g_needdst[n >> 5] >> (n & 31)) & 1u;
        unsigned m = __ballot_sync(0xffffffffu, a);
        if (m) {
            int leader = __ffs(m) - 1;
            int pos = 0;
            if (lane == leader) pos = atomicAdd(&g_cnt[h * 4 + 2], __popc(m));
            pos = __shfl_sync(0xffffffffu, pos, leader);
            pos += __popc(m & ((1u << lane) - 1));
            if (a) g_plist[h * NN + pos] = 2 * n + 1;
        }
    }
}

// ---------------------------------------------------------------- per-node edge precompute (job list)
__global__ __launch_bounds__(256) void pre_kernel(
    const float* __restrict__ x, const float* __restrict__ Wm,
    const float* __restrict__ bm, int h)
{
    __shared__ float Ws[52 * 64];
    __shared__ float bs[64];
    for (int i = threadIdx.x; i < 52 * 64; i += 256) Ws[i] = Wm[i];
    if (threadIdx.x < 64) bs[threadIdx.x] = bm[threadIdx.x];
    __syncthreads();

    int i = blockIdx.x * 256 + threadIdx.x;
    if (i >= g_cnt[h * 4 + 2]) return;
    int job  = g_plist[h * NN + i];
    int n    = job >> 1;
    int half = job & 1;

    ull acc[32];
#pragma unroll
    for (int j = 0; j < 32; j++)
        acc[j] = half ? 0ull : pk(bs[2 * j], bs[2 * j + 1]);

    const float2* xr = (const float2*)(x + (size_t)n * IN_F);
    const int rbase = half * IN_F;
#pragma unroll
    for (int kk = 0; kk < 13; kk++) {
        float2 xv = xr[kk];
#pragma unroll
        for (int hh = 0; hh < 2; hh++) {
            ull v = pk2(hh ? xv.y : xv.x);
            const ulonglong2* wr = (const ulonglong2*)&Ws[(rbase + 2 * kk + hh) * 64];
#pragma unroll
            for (int j = 0; j < 16; j++) {
                ulonglong2 w = wr[j];
                acc[2 * j]     = fma2(v, w.x, acc[2 * j]);
                acc[2 * j + 1] = fma2(v, w.y, acc[2 * j + 1]);
            }
        }
    }
    float4* dst = (float4*)(g_P + (size_t)n * 128 + half * 64);
#pragma unroll
    for (int j = 0; j < 16; j++) {
        float2 a = upk(acc[2 * j]), b = upk(acc[2 * j + 1]);
        dst[j] = make_float4(a.x, a.y, b.x, b.y);
    }
}

// ---------------------------------------------------------------- edges (active only, red.v2)
__global__ __launch_bounds__(256) void edge_kernel(const float* __restrict__ ea,
                                                   const float* __restrict__ Wm, int h)
{
    __shared__ float Ws[15 * 64];
    for (int i = threadIdx.x; i < 15 * 64; i += 256) Ws[i] = Wm[52 * 64 + i];
    __syncthreads();

    const int l  = threadIdx.x & 31;
    const int gw = blockIdx.x * 8 + (threadIdx.x >> 5);
    const int W  = gridDim.x * 8;
    const int ec = g_cnt[h * 4];

    for (int i = gw; i < ec; i += W) {
        int4 sde = g_sde[h * NE2 + i];
        ull ps = *(const ull*)(g_P + (size_t)sde.x * 128 + 2 * l);
        ull pd = *(const ull*)(g_P + (size_t)sde.y * 128 + 64 + 2 * l);
        ull acc = add2(ps, pd);
        const float* er = ea + (size_t)sde.z * 15;
#pragma unroll
        for (int k = 0; k < 15; k++) {
            ull w = *(const ull*)&Ws[k * 64 + 2 * l];
            acc = fma2(pk2(er[k]), w, acc);
        }
        float2 a = upk(acc);
        redv2(g_agg + (size_t)sde.y * 64 + 2 * l, fmaxf(a.x, 0.f), fmaxf(a.y, 0.f));
    }
}

// ---------------------------------------------------------------- nodes (sampled only)
__global__ __launch_bounds__(256) void node_kernel(
    const float* __restrict__ x, const float* __restrict__ Wn,
    const float* __restrict__ bn, int h)
{
    __shared__ float Ws[90 * 64];
    __shared__ float bs[64];
    for (int i = threadIdx.x; i < 90 * 64; i += 256) Ws[i] = Wn[i];
    if (threadIdx.x < 64) bs[threadIdx.x] = bn[threadIdx.x];
    __syncthreads();

    int i = blockIdx.x * 256 + threadIdx.x;
    if (i >= g_cnt[h * 4 + 1]) return;
    int n = g_nlist[h * NN2 + i];

    ull acc[32];
#pragma unroll
    for (int j = 0; j < 32; j++) acc[j] = pk(bs[2 * j], bs[2 * j + 1]);

    const float2* xr = (const float2*)(x + (size_t)n * IN_F);
#pragma unroll
    for (int kk = 0; kk < 13; kk++) {
        float2 xv = xr[kk];
#pragma unroll
        for (int hh = 0; hh < 2; hh++) {
            ull v = pk2(hh ? xv.y : xv.x);
            const ulonglong2* wr = (const ulonglong2*)&Ws[(2 * kk + hh) * 64];
#pragma unroll
            for (int j = 0; j < 16; j++) {
                ulonglong2 w = wr[j];
                acc[2 * j]     = fma2(v, w.x, acc[2 * j]);
                acc[2 * j + 1] = fma2(v, w.y, acc[2 * j + 1]);
            }
        }
    }
    const float4* ar = (const float4*)(g_agg + (size_t)n * 64);
#pragma unroll
    for (int kk = 0; kk < 16; kk++) {
        float4 av = ar[kk];
#pragma unroll
        for (int hh = 0; hh < 4; hh++) {
            float vf = hh == 0 ? av.x : hh == 1 ? av.y : hh == 2 ? av.z : av.w;
            ull v = pk2(vf);
            const ulonglong2* wr = (const ulonglong2*)&Ws[(IN_F + 4 * kk + hh) * 64];
#pragma unroll
            for (int j = 0; j < 16; j++) {
                ulonglong2 w = wr[j];
                acc[2 * j]     = fma2(v, w.x, acc[2 * j]);
                acc[2 * j + 1] = fma2(v, w.y, acc[2 * j + 1]);
            }
        }
    }
    float4* dst = (float4*)(g_conv + (size_t)n * 64);
#pragma unroll
    for (int j = 0; j < 16; j++) {
        float2 a = upk(acc[2 * j]), b = upk(acc[2 * j + 1]);
        dst[j] = make_float4(fmaxf(a.x, 0.f), fmaxf(a.y, 0.f),
                             fmaxf(b.x, 0.f), fmaxf(b.y, 0.f));
    }
}

// ---------------------------------------------------------------- fused sampled pipeline
// 64 rows/CTA, 512 threads. Triple-buffered ring, specialized loops, 1 sync/chunk.
#define O_NCT 0            // [64][68]
#define O_A2  4352         // [64][20]
#define O_XT  5632         // [64][132]
#define O_HT  14080        // [64][132]
#define O_WST 22528        // 3 x [16][520]
#define WBUF  8320
#define SMEM_F 47488       // 189952 bytes

__global__ __launch_bounds__(512, 1) void sample_kernel(
    const int* __restrict__ sidx_g, const float* __restrict__ gm,
    const float* __restrict__ be,
    const float* __restrict__ bd1,
    const float* __restrict__ Wd2, const float* __restrict__ bd2,
    float* __restrict__ out, int h)
{
    extern __shared__ float sm[];
    float* nct = sm + O_NCT;
    float* A2  = sm + O_A2;
    float* Xt  = sm + O_XT;
    float* Ht  = sm + O_HT;
    float* Wst = sm + O_WST;
    __shared__ float gmrow[10];
    __shared__ int   sidx[64];

    const int t    = threadIdx.x;
    const int base = h * NS2 + blockIdx.x * 64;
    const uint32_t wst_u = (uint32_t)__cvta_generic_to_shared(Wst);

    if (t < 64) sidx[t] = sidx_g[base + t];
    if (t < 10) gmrow[t] = gm[(base >> 10) * 10 + t];

    auto prefetch = [&](int c2) {
        uint32_t db = wst_u + (uint32_t)((c2 % 3) * WBUF) * 4;
        if (c2 < 4) {
            int bpos = t * 4; int kk = bpos >> 7, n = bpos & 127;
            cp16(db + (uint32_t)(kk * 520 + n) * 4, g_We_t + c2 * 2048 + kk * 128 + n);
        } else if (c2 < 36) {
#pragma unroll
            for (int ii = 0; ii < 4; ii++) {
                int bpos = (ii * 512 + t) * 4; int kk = bpos >> 9, n = bpos & 511;
                cp16(db + (uint32_t)(kk * 520 + n) * 4,
                     g_Wl + (size_t)(c2 - 4) * 8192 + kk * 512 + n);
            }
        } else if (c2 < 52) {
            if (t < 256) {
                int bpos = t * 4; int kk = bpos >> 6, n = bpos & 63;
                cp16(db + (uint32_t)(kk * 520 + n) * 4,
                     g_Wd1_t + (c2 - 36) * 1024 + kk * 64 + n);
            }
        }
        CP_COMMIT();
    };
    prefetch(0);
    prefetch(1);

    __syncthreads();   // sidx visible

    float* out_nc = out;
    float* out_h1 = out + (size_t)NS * 64;
    float* out_c1 = out_h1 + (size_t)NS * 128;
    float* out_h2 = out_c1 + (size_t)NS * 128;
    float* out_c2 = out_h2 + (size_t)NS * 128;
    float* out_y  = out_c2 + (size_t)NS * 128;

    for (int idx = t; idx < 64 * 64; idx += 512) {
        int r = idx >> 6, c = idx & 63;
        float v = g_conv[(size_t)sidx[r] * 64 + c];
        nct[r * 68 + c] = tf32v(v);
        out_nc[(size_t)(base + r) * 64 + c] = v;
    }
    for (int idx = t; idx < 64 * 20; idx += 512) {
        int r = idx / 20, kk = idx - r * 20;
        A2[idx] = (kk < 10) ? tf32v(g_conv[(size_t)sidx[r] * 64 + 54 + kk]) : 0.f;
    }
    __syncthreads();

    const int w    = t >> 5;
    const int lane = t & 31;
    const int g8   = lane >> 2;
    const int cc   = lane & 3;
    const int j0   = w * 8;
    const int col0 = j0 + 2 * cc, col1 = col0 + 1;

    float acc[64];
#pragma unroll
    for (int i = 0; i < 64; i++) acc[i] = 0.f;

    // ================= encoder: chunks 0..3 =================
#pragma unroll 1
    for (int c = 0; c < 4; c++) {
        CP_WAIT(1);
        __syncthreads();
        prefetch(c + 2);
        const float* wb = Wst + (c % 3) * WBUF;
#pragma unroll
        for (int ks = 0; ks < 2; ks++) {
            int k0 = c * 16 + ks * 8;
            uint32_t b0 = ldb(&wb[(ks * 8 + cc) * 520 + j0 + g8]);
            uint32_t b1 = ldb(&wb[(ks * 8 + cc + 4) * 520 + j0 + g8]);
#pragma unroll
            for (int mt = 0; mt < 4; mt++) {
                int r0 = mt * 16 + g8;
                uint32_t a[4];
                a[0] = ldb(&nct[r0 * 68 + k0 + cc]);
                a[1] = ldb(&nct[(r0 + 8) * 68 + k0 + cc]);
                a[2] = ldb(&nct[r0 * 68 + k0 + cc + 4]);
                a[3] = ldb(&nct[(r0 + 8) * 68 + k0 + cc + 4]);
                mma8(acc + mt * 4, a, b0, b1);
            }
        }
    }

    // ---- gm-correction mma + encoder epilogue
    {
        const float* wb = Wst + 0 * WBUF;   // buffer 0 holds chunk 3
#pragma unroll
        for (int ks = 0; ks < 2; ks++) {
            int k0 = ks * 8;
            uint32_t b0 = ldb(&wb[(6 + k0 + cc) * 520 + j0 + g8]);
            uint32_t b1 = ldb(&wb[(6 + k0 + cc + 4) * 520 + j0 + g8]);
#pragma unroll
            for (int mt = 0; mt < 4; mt++) {
                int r0 = mt * 16 + g8;
                uint32_t a[4];
                a[0] = ldb(&A2[r0 * 20 + k0 + cc]);
                a[1] = ldb(&A2[(r0 + 8) * 20 + k0 + cc]);
                a[2] = ldb(&A2[r0 * 20 + k0 + cc + 4]);
                a[3] = ldb(&A2[(r0 + 8) * 20 + k0 + cc + 4]);
                mma8(acc + 16 + mt * 4, a, b0, b1);
            }
        }
        float be0 = be[col0], be1 = be[col1];
        float gs0 = 0.f, gs1 = 0.f;
#pragma unroll
        for (int k = 0; k < 10; k++) {
            gs0 = fmaf(gmrow[k], wb[(6 + k) * 520 + col0], gs0);
            gs1 = fmaf(gmrow[k], wb[(6 + k) * 520 + col1], gs1);
        }
#pragma unroll
        for (int mt = 0; mt < 4; mt++) {
#pragma unroll
            for (int pp = 0; pp < 2; pp++) {
                int row = mt * 16 + g8 + pp * 8;
                float hp0 = acc[mt * 4 + pp * 2],      hp1 = acc[mt * 4 + pp * 2 + 1];
                float cr0 = acc[16 + mt * 4 + pp * 2], cr1 = acc[16 + mt * 4 + pp * 2 + 1];
                *(float2*)(Xt + row * 132 + col0) =
                    make_float2(tf32v(fmaxf(hp0 - cr0 + gs0 + be0, 0.f)),
                                tf32v(fmaxf(hp1 - cr1 + gs1 + be1, 0.f)));
                *(float2*)(Ht + row * 132 + col0) =
                    make_float2(tf32v(fmaxf(hp0 + be0, 0.f)),
                                tf32v(fmaxf(hp1 + be1, 0.f)));
            }
        }
#pragma unroll
        for (int i = 0; i < 64; i++) acc[i] = 0.f;
    }
    __syncthreads();

    // ================= LSTM cells: chunks 4..35 =================
#pragma unroll 1
    for (int cell = 0; cell < 2; cell++) {
        const int cbase = 4 + cell * 16;
#pragma unroll 1
        for (int cl = 0; cl < 16; cl++) {
            const int c = cbase + cl;
            CP_WAIT(1);
            __syncthreads();
            prefetch(c + 2);
            const int kl = cl * 16;
            const float* wb = Wst + (c % 3) * WBUF;
#pragma unroll
            for (int ks = 0; ks < 2; ks++) {
                int kg = kl + ks * 8;
                const float* At_ = (kg < 128) ? (Xt + kg) : (Ht + (kg - 128));
                uint32_t afr[4][4];
#pragma unroll
                for (int mt = 0; mt < 4; mt++) {
                    int r0 = mt * 16 + g8;
                    afr[mt][0] = ldb(&At_[r0 * 132 + cc]);
                    afr[mt][1] = ldb(&At_[(r0 + 8) * 132 + cc]);
                    afr[mt][2] = ldb(&At_[r0 * 132 + cc + 4]);
                    afr[mt][3] = ldb(&At_[(r0 + 8) * 132 + cc + 4]);
                }
#pragma unroll
                for (int q = 0; q < 4; q++) {
                    int ncol = q * 128 + j0 + g8;
                    uint32_t b0 = ldb(&wb[(ks * 8 + cc) * 520 + ncol]);
                    uint32_t b1 = ldb(&wb[(ks * 8 + cc + 4) * 520 + ncol]);
#pragma unroll
                    for (int mt = 0; mt < 4; mt++)
                        mma8(acc + mt * 16 + q * 4, afr[mt], b0, b1);
                }
            }
        }

        __syncthreads();
        {
            const float* bc = g_bc + cell * 512;
            float* oH = cell ? out_h2 : out_h1;
            float* oC = cell ? out_c2 : out_c1;
#pragma unroll
            for (int mt = 0; mt < 4; mt++) {
#pragma unroll
                for (int pp = 0; pp < 2; pp++) {
                    int row = mt * 16 + g8 + pp * 8;
                    int ib  = mt * 16 + pp * 2;
                    float vi0 = acc[ib + 0]  + bc[col0],       vi1 = acc[ib + 1]  + bc[col1];
                    float vf0 = acc[ib + 4]  + bc[128 + col0], vf1 = acc[ib + 5]  + bc[128 + col1];
                    float vg0 = acc[ib + 8]  + bc[256 + col0], vg1 = acc[ib + 9]  + bc[256 + col1];
                    float vo0 = acc[ib + 12] + bc[384 + col0], vo1 = acc[ib + 13] + bc[384 + col1];
                    float cp0 = Ht[row * 132 + col0], cp1 = Ht[row * 132 + col1];
                    float cv0 = fsig(vf0) * cp0 + fsig(vi0) * ftanh(vg0);
                    float cv1 = fsig(vf1) * cp1 + fsig(vi1) * ftanh(vg1);
                    float hv0 = fsig(vo0) * ftanh(cv0);
                    float hv1 = fsig(vo1) * ftanh(cv1);
                    size_t gi = (size_t)(base + row) * 128 + col0;
                    *(float2*)(oH + gi) = make_float2(hv0, hv1);
                    *(float2*)(oC + gi) = make_float2(cv0, cv1);
                    if (cell == 0) {
                        float nx0 = (col0 >= 118) ? gmrow[col0 - 118] : hv0;
                        float nx1 = (col1 >= 118) ? gmrow[col1 - 118] : hv1;
                        *(float2*)(Xt + row * 132 + col0) = make_float2(tf32v(nx0), tf32v(nx1));
                    } else {
                        *(float2*)(Xt + row * 132 + col0) = make_float2(tf32v(hv0), tf32v(hv1));
                        *(float2*)(Ht + row * 132 + col0) = make_float2(tf32v(cv0), tf32v(cv1));
                    }
                }
            }
#pragma unroll
            for (int i = 0; i < 64; i++) acc[i] = 0.f;
        }
        __syncthreads();
    }

    // ================= decoder: chunks 36..51 =================
    {
        const int n0  = (w & 7) * 8;
        const int mt0 = (w >> 3) * 2;
#pragma unroll 1
        for (int dl = 0; dl < 16; dl++) {
            const int c = 36 + dl;
            CP_WAIT(1);
            __syncthreads();
            prefetch(c + 2);
            const float* wb = Wst + (c % 3) * WBUF;
#pragma unroll
            for (int ks = 0; ks < 2; ks++) {
                int kg = dl * 16 + ks * 8;
                const float* At_ = (kg < 128) ? (Xt + kg) : (Ht + (kg - 128));
                uint32_t b0 = ldb(&wb[(ks * 8 + cc) * 520 + n0 + g8]);
                uint32_t b1 = ldb(&wb[(ks * 8 + cc + 4) * 520 + n0 + g8]);
#pragma unroll
                for (int m = 0; m < 2; m++) {
                    int r0 = (mt0 + m) * 16 + g8;
                    uint32_t a[4];
                    a[0] = ldb(&At_[r0 * 132 + cc]);
                    a[1] = ldb(&At_[(r0 + 8) * 132 + cc]);
                    a[2] = ldb(&At_[r0 * 132 + cc + 4]);
                    a[3] = ldb(&At_[(r0 + 8) * 132 + cc + 4]);
                    mma8(acc + m * 4, a, b0, b1);
                }
            }
        }
        __syncthreads();
        int c0 = n0 + 2 * cc, c1 = c0 + 1;
        float b0 = bd1[c0], b1 = bd1[c1];
#pragma unroll
        for (int m = 0; m < 2; m++) {
#pragma unroll
            for (int pp = 0; pp < 2; pp++) {
                int row = (mt0 + m) * 16 + g8 + pp * 8;
                float v0 = fmaxf(acc[m * 4 + pp * 2]     + b0, 0.f);
                float v1 = fmaxf(acc[m * 4 + pp * 2 + 1] + b1, 0.f);
                *(float2*)(nct + row * 68 + c0) = make_float2(v0, v1);
            }
        }
    }
    __syncthreads();

    // y = d1 @ Wd2 + b
    if (t < 384) {
        int r = t / 6, c = t - r * 6;
        float accy = bd2[c];
#pragma unroll
        for (int k = 0; k < 64; k++) accy = fmaf(nct[r * 68 + k], Wd2[k * 6 + c], accy);
        out_y[(size_t)(base + r) * 6 + c] = accy;
    }
}

// ----------------------------------------------------------------
extern "C" void kernel_launch(void* const* d_in, const int* in_sizes, int n_in,
                              void* d_out, int out_size)
{
    const float* x    = (const float*)d_in[0];
    const int*   ei   = (const int*)d_in[1];
    const float* ea   = (const float*)d_in[2];
    const int*   si   = (const int*)d_in[3];
    const float* gm   = (const float*)d_in[4];
    const float* Wm   = (const float*)d_in[5];
    const float* bm   = (const float*)d_in[6];
    const float* Wn   = (const float*)d_in[7];
    const float* bn   = (const float*)d_in[8];
    const float* We   = (const float*)d_in[9];
    const float* be_  = (const float*)d_in[10];
    const float* Wih0 = (const float*)d_in[11];
    const float* Whh0 = (const float*)d_in[12];
    const float* bih0 = (const float*)d_in[13];
    const float* bhh0 = (const float*)d_in[14];
    const float* Wih1 = (const float*)d_in[15];
    const float* Whh1 = (const float*)d_in[16];
    const float* bih1 = (const float*)d_in[17];
    const float* bhh1 = (const float*)d_in[18];
    const float* Wd1  = (const float*)d_in[19];
    const float* bd1  = (const float*)d_in[20];
    const float* Wd2  = (const float*)d_in[21];
    const float* bd2  = (const float*)d_in[22];
    float* out = (float*)d_out;

    // one-time stream/event setup (first call = correctness run, outside capture)
    static cudaStream_t s1 = nullptr;
    static cudaEvent_t evF = nullptr, evP = nullptr, evJ = nullptr;
    if (!s1) {
        cudaStreamCreateWithFlags(&s1, cudaStreamNonBlocking);
        cudaEventCreateWithFlags(&evF, cudaEventDisableTiming);
        cudaEventCreateWithFlags(&evP, cudaEventDisableTiming);
        cudaEventCreateWithFlags(&evJ, cudaEventDisableTiming);
        const int smem_bytes = SMEM_F * 4;
        cudaFuncSetAttribute(sample_kernel,
                             cudaFuncAttributeMaxDynamicSharedMemorySize, smem_bytes);
    }
    const int smem_bytes = SMEM_F * 4;   // 189952

    // fork side stream off the capture (default) stream
    cudaEventRecord(evF, 0);
    cudaStreamWaitEvent(s1, evF, 0);

    // ---- stream s1: prep (weights) then half-1 chain
    prep_kernel<<<1124, 256, 0, s1>>>(Wih0, Whh0, Wih1, Whh1, We, Wd1,
                                      bih0, bhh0, bih1, bhh1);
    cudaEventRecord(evP, s1);
    zero_tables_kernel<<<49, 256, 0, s1>>>(1);
    flag_zero_kernel<<<NS2 / 8, 256, 0, s1>>>(si, 1);
    compact_edges_kernel<<<NE2 / 256, 256, 0, s1>>>(ei, 1);
    compact_nodes_kernel<<<NN2 / 256, 256, 0, s1>>>(1);
    pre_kernel<<<NN / 256, 256, 0, s1>>>(x, Wm, bm, 1);
    edge_kernel<<<512, 256, 0, s1>>>(ea, Wm, 1);
    node_kernel<<<NS2 / 256, 256, 0, s1>>>(x, Wn, bn, 1);
    sample_kernel<<<NS2 / 64, 512, smem_bytes, s1>>>(
        si, gm, be_, bd1, Wd2, bd2, out, 1);
    cudaEventRecord(evJ, s1);

    // ---- default stream: half-0 chain
    zero_tables_kernel<<<49, 256>>>(0);
    flag_zero_kernel<<<NS2 / 8, 256>>>(si, 0);
    compact_edges_kernel<<<NE2 / 256, 256>>>(ei, 0);
    compact_nodes_kernel<<<NN2 / 256, 256>>>(0);
    pre_kernel<<<NN / 256, 256>>>(x, Wm, bm, 0);
    edge_kernel<<<512, 256>>>(ea, Wm, 0);
    node_kernel<<<NS2 / 256, 256>>>(x, Wn, bn, 0);
    cudaStreamWaitEvent(0, evP, 0);        // sample needs prepped weights
    sample_kernel<<<NS2 / 64, 512, smem_bytes>>>(
        si, gm, be_, bd1, Wd2, bd2, out, 0);

    // join
    cudaStreamWaitEvent(0, evJ, 0);
}

// round 12
// speedup vs baseline: 1.2959x; 1.1095x over previous
#include <cuda_runtime.h>
#include <cuda_fp16.h>
#include <math.h>
#include <stdint.h>

#define NN (64*4096)
#define NE (64*16384)
#define NS (64*1024)
#define NN2 (NN/2)
#define NE2 (NE/2)
#define NS2 (NS/2)
#define IN_F 26

typedef unsigned long long ull;

__device__ __align__(16) float g_agg[(size_t)NN * 64];
__device__ __align__(16) float g_conv[(size_t)NN * 64];
__device__ __align__(16) float g_P[(size_t)NN * 128];
__device__ unsigned g_flagbits[NN / 32];
__device__ unsigned g_needsrc[NN / 32];
__device__ unsigned g_needdst[NN / 32];
__device__ int4  g_sde[NE];
__device__ int   g_nlist[NN];
__device__ int   g_plist[2 * NN];
__device__ int   g_cnt[8];
// fp16-stored weights, SAME logical layout as validated fp32 version
__device__ __align__(16) __half g_Wlh[512 * 512];
__device__ __align__(16) __half g_Weh[64 * 128];
__device__ __align__(16) __half g_Wd1h[256 * 64];
__device__ __align__(16) float  g_bc[2 * 512];

__device__ __forceinline__ ull pk(float lo, float hi) {
    ull r; asm("mov.b64 %0, {%1, %2};" : "=l"(r) : "f"(lo), "f"(hi)); return r;
}
__device__ __forceinline__ ull pk2(float v) { return pk(v, v); }
__device__ __forceinline__ float2 upk(ull v) {
    float2 r; asm("mov.b64 {%0, %1}, %2;" : "=f"(r.x), "=f"(r.y) : "l"(v)); return r;
}
__device__ __forceinline__ ull fma2(ull a, ull b, ull c) {
    ull d; asm("fma.rn.f32x2 %0, %1, %2, %3;" : "=l"(d) : "l"(a), "l"(b), "l"(c)); return d;
}
__device__ __forceinline__ ull add2(ull a, ull b) {
    ull d; asm("add.rn.f32x2 %0, %1, %2;" : "=l"(d) : "l"(a), "l"(b)); return d;
}
__device__ __forceinline__ float fsig(float x)  { return __fdividef(1.f, 1.f + __expf(-x)); }
__device__ __forceinline__ float ftanh(float x) { return 1.f - __fdividef(2.f, 1.f + __expf(2.f * x)); }

__device__ __forceinline__ float tf32v(float f) {
    uint32_t r; asm("cvt.rna.tf32.f32 %0, %1;" : "=r"(r) : "f"(f));
    return __uint_as_float(r);
}
__device__ __forceinline__ void mma8(float* d, const uint32_t* a, uint32_t b0, uint32_t b1) {
    asm volatile(
        "mma.sync.aligned.m16n8k8.row.col.f32.tf32.tf32.f32 "
        "{%0,%1,%2,%3}, {%4,%5,%6,%7}, {%8,%9}, {%0,%1,%2,%3};"
        : "+f"(d[0]), "+f"(d[1]), "+f"(d[2]), "+f"(d[3])
        : "r"(a[0]), "r"(a[1]), "r"(a[2]), "r"(a[3]), "r"(b0), "r"(b1));
}
__device__ __forceinline__ uint32_t ldb(const float* p) { return __float_as_uint(*p); }
__device__ __forceinline__ uint32_t ldh(const __half* p) {
    return __float_as_uint(__half2float(*p));   // exact: fp16 subset of tf32
}
__device__ __forceinline__ void cp16(uint32_t dst, const void* src) {
    asm volatile("cp.async.cg.shared.global [%0], [%1], 16;" :: "r"(dst), "l"(src));
}
#define CP_COMMIT() asm volatile("cp.async.commit_group;")
#define CP_WAIT(n)  asm volatile("cp.async.wait_group " #n ";")
__device__ __forceinline__ void redv2(float* p, float a, float b) {
    asm volatile("red.global.add.v2.f32 [%0], {%1, %2};" :: "l"(p), "f"(a), "f"(b) : "memory");
}

// ---------------- prep: fp16 weight conversion ----------------
__global__ __launch_bounds__(256) void prep_kernel(
    const float* __restrict__ Wih0, const float* __restrict__ Whh0,
    const float* __restrict__ Wih1, const float* __restrict__ Whh1,
    const float* __restrict__ We,   const float* __restrict__ Wd1,
    const float* __restrict__ bih0, const float* __restrict__ bhh0,
    const float* __restrict__ bih1, const float* __restrict__ bhh1)
{
    int i = blockIdx.x * 256 + threadIdx.x;
    if (i < 262144) {
        int cell = i >> 17, r = (i >> 9) & 255, n = i & 511;
        const float* W = (r < 128) ? (cell ? Wih1 : Wih0) : (cell ? Whh1 : Whh0);
        g_Wlh[i] = __float2half(W[(r & 127) * 512 + n]);
    } else if (i < 270336) {
        int j = i - 262144; g_Weh[j] = __float2half(We[j]);
    } else if (i < 286720) {
        int j = i - 270336; g_Wd1h[j] = __float2half(Wd1[j]);
    } else if (i < 287744) {
        int j = i - 286720; int cell = j >> 9; int n = j & 511;
        g_bc[j] = cell ? (bih1[n] + bhh1[n]) : (bih0[n] + bhh0[n]);
    }
}

__global__ __launch_bounds__(256) void zero_tables_kernel(int h) {
    int i = blockIdx.x * 256 + threadIdx.x;
    int b = h * (NN2 / 32);
    if (i < 4096) g_flagbits[b + i] = 0u;
    else if (i < 8192) g_needsrc[b + i - 4096] = 0u;
    else if (i < 12288) g_needdst[b + i - 8192] = 0u;
    else if (i < 12292) g_cnt[h * 4 + i - 12288] = 0;
}

__global__ __launch_bounds__(256) void flag_zero_kernel(const int* __restrict__ si, int h) {
    int gw = blockIdx.x * 8 + (threadIdx.x >> 5);
    int l  = threadIdx.x & 31;
    int n  = si[h * NS2 + gw];
    if (l == 0) atomicOr(&g_flagbits[n >> 5], 1u << (n & 31));
    ((float2*)(g_agg + (size_t)n * 64))[l] = make_float2(0.f, 0.f);
}

__global__ __launch_bounds__(256) void compact_edges_kernel(const int* __restrict__ ei, int h) {
    int e = h * NE2 + blockIdx.x * 256 + threadIdx.x;
    int d = ei[NE + e];
    bool act = (g_flagbits[d >> 5] >> (d & 31)) & 1u;
    unsigned m = __ballot_sync(0xffffffffu, act);
    if (m) {
        int lane = threadIdx.x & 31;
        int leader = __ffs(m) - 1;
        int pos = 0;
        if (lane == leader) pos = atomicAdd(&g_cnt[h * 4], __popc(m));
        pos = __shfl_sync(0xffffffffu, pos, leader);
        pos += __popc(m & ((1u << lane) - 1));
        if (act) {
            int s = ei[e];
            g_sde[h * NE2 + pos] = make_int4(s, d, e, 0);
            atomicOr(&g_needsrc[s >> 5], 1u << (s & 31));
            atomicOr(&g_needdst[d >> 5], 1u << (d & 31));
        }
    }
}

__global__ __launch_bounds__(256) void compact_nodes_kernel(int h) {
    int n = h * NN2 + blockIdx.x * 256 + threadIdx.x;
    int lane = threadIdx.x & 31;
    {
        bool a = (g_flagbits[n >> 5] >> (n & 31)) & 1u;
        unsigned m = __ballot_sync(0xffffffffu, a);
        if (m) {
            int leader = __ffs(m) - 1;
            int pos = 0;
            if (lane == leader) pos = atomicAdd(&g_cnt[h * 4 + 1], __popc(m));
            pos = __shfl_sync(0xffffffffu, pos, leader);
            pos += __popc(m & ((1u << lane) - 1));
            if (a) g_nlist[h * NN2 + pos] = n;
        }
    }
    {
        bool a = (g_needsrc[n >> 5] >> (n & 31)) & 1u;
        unsigned m = __ballot_sync(0xffffffffu, a);
        if (m) {
            int leader = __ffs(m) - 1;
            int pos = 0;
            if (lane == leader) pos = atomicAdd(&g_cnt[h * 4 + 2], __popc(m));
            pos = __shfl_sync(0xffffffffu, pos, leader);
            pos += __popc(m & ((1u << lane) - 1));
            if (a) g_plist[h * NN + pos] = 2 * n;
        }
    }
    {
        bool a = (g_needdst[n >> 5] >> (n & 31)) & 1u;
        unsigned m = __ballot_sync(0xffffffffu, a);
        if (m) {
            int leader = __ffs(m) - 1;
            int pos = 0;
            if (lane == leader) pos = atomicAdd(&g_cnt[h * 4 + 2], __popc(m));
            pos = __shfl_sync(0xffffffffu, pos, leader);
            pos += __popc(m & ((1u << lane) - 1));
            if (a) g_plist[h * NN + pos] = 2 * n + 1;
        }
    }
}

__global__ __launch_bounds__(256) void pre_kernel(
    const float* __restrict__ x, const float* __restrict__ Wm,
    const float* __restrict__ bm, int h)
{
    __shared__ float Ws[52 * 64];
    __shared__ float bs[64];
    for (int i = threadIdx.x; i < 52 * 64; i += 256) Ws[i] = Wm[i];
    if (threadIdx.x < 64) bs[threadIdx.x] = bm[threadIdx.x];
    __syncthreads();

    int i = blockIdx.x * 256 + threadIdx.x;
    if (i >= g_cnt[h * 4 + 2]) return;
    int job  = g_plist[h * NN + i];
    int n    = job >> 1;
    int half = job & 1;

    ull acc[32];
#pragma unroll
    for (int j = 0; j < 32; j++)
        acc[j] = half ? 0ull : pk(bs[2 * j], bs[2 * j + 1]);

    const float2* xr = (const float2*)(x + (size_t)n * IN_F);
    const int rbase = half * IN_F;
#pragma unroll
    for (int kk = 0; kk < 13; kk++) {
        float2 xv = xr[kk];
#pragma unroll
        for (int hh = 0; hh < 2; hh++) {
            ull v = pk2(hh ? xv.y : xv.x);
            const ulonglong2* wr = (const ulonglong2*)&Ws[(rbase + 2 * kk + hh) * 64];
#pragma unroll
            for (int j = 0; j < 16; j++) {
                ulonglong2 w = wr[j];
                acc[2 * j]     = fma2(v, w.x, acc[2 * j]);
                acc[2 * j + 1] = fma2(v, w.y, acc[2 * j + 1]);
            }
        }
    }
    float4* dst = (float4*)(g_P + (size_t)n * 128 + half * 64);
#pragma unroll
    for (int j = 0; j < 16; j++) {
        float2 a = upk(acc[2 * j]), b = upk(acc[2 * j + 1]);
        dst[j] = make_float4(a.x, a.y, b.x, b.y);
    }
}

__global__ __launch_bounds__(256) void edge_kernel(const float* __restrict__ ea,
                                                   const float* __restrict__ Wm, int h)
{
    __shared__ float Ws[15 * 64];
    for (int i = threadIdx.x; i < 15 * 64; i += 256) Ws[i] = Wm[52 * 64 + i];
    __syncthreads();

    const int l  = threadIdx.x & 31;
    const int gw = blockIdx.x * 8 + (threadIdx.x >> 5);
    const int W  = gridDim.x * 8;
    const int ec = g_cnt[h * 4];

    for (int i = gw; i < ec; i += W) {
        int4 sde = g_sde[h * NE2 + i];
        ull ps = *(const ull*)(g_P + (size_t)sde.x * 128 + 2 * l);
        ull pd = *(const ull*)(g_P + (size_t)sde.y * 128 + 64 + 2 * l);
        ull acc = add2(ps, pd);
        const float* er = ea + (size_t)sde.z * 15;
#pragma unroll
        for (int k = 0; k < 15; k++) {
            ull w = *(const ull*)&Ws[k * 64 + 2 * l];
            acc = fma2(pk2(er[k]), w, acc);
        }
        float2 a = upk(acc);
        redv2(g_agg + (size_t)sde.y * 64 + 2 * l, fmaxf(a.x, 0.f), fmaxf(a.y, 0.f));
    }
}

__global__ __launch_bounds__(256) void node_kernel(
    const float* __restrict__ x, const float* __restrict__ Wn,
    const float* __restrict__ bn, int h)
{
    __shared__ float Ws[90 * 64];
    __shared__ float bs[64];
    for (int i = threadIdx.x; i < 90 * 64; i += 256) Ws[i] = Wn[i];
    if (threadIdx.x < 64) bs[threadIdx.x] = bn[threadIdx.x];
    __syncthreads();

    int i = blockIdx.x * 256 + threadIdx.x;
    if (i >= g_cnt[h * 4 + 1]) return;
    int n = g_nlist[h * NN2 + i];

    ull acc[32];
#pragma unroll
    for (int j = 0; j < 32; j++) acc[j] = pk(bs[2 * j], bs[2 * j + 1]);

    const float2* xr = (const float2*)(x + (size_t)n * IN_F);
#pragma unroll
    for (int kk = 0; kk < 13; kk++) {
        float2 xv = xr[kk];
#pragma unroll
        for (int hh = 0; hh < 2; hh++) {
            ull v = pk2(hh ? xv.y : xv.x);
            const ulonglong2* wr = (const ulonglong2*)&Ws[(2 * kk + hh) * 64];
#pragma unroll
            for (int j = 0; j < 16; j++) {
                ulonglong2 w = wr[j];
                acc[2 * j]     = fma2(v, w.x, acc[2 * j]);
                acc[2 * j + 1] = fma2(v, w.y, acc[2 * j + 1]);
            }
        }
    }
    const float4* ar = (const float4*)(g_agg + (size_t)n * 64);
#pragma unroll
    for (int kk = 0; kk < 16; kk++) {
        float4 av = ar[kk];
#pragma unroll
        for (int hh = 0; hh < 4; hh++) {
            float vf = hh == 0 ? av.x : hh == 1 ? av.y : hh == 2 ? av.z : av.w;
            ull v = pk2(vf);
            const ulonglong2* wr = (const ulonglong2*)&Ws[(IN_F + 4 * kk + hh) * 64];
#pragma unroll
            for (int j = 0; j < 16; j++) {
                ulonglong2 w = wr[j];
                acc[2 * j]     = fma2(v, w.x, acc[2 * j]);
                acc[2 * j + 1] = fma2(v, w.y, acc[2 * j + 1]);
            }
        }
    }
    float4* dst = (float4*)(g_conv + (size_t)n * 64);
#pragma unroll
    for (int j = 0; j < 16; j++) {
        float2 a = upk(acc[2 * j]), b = upk(acc[2 * j + 1]);
        dst[j] = make_float4(fmaxf(a.x, 0.f), fmaxf(a.y, 0.f),
                             fmaxf(b.x, 0.f), fmaxf(b.y, 0.f));
    }
}

// ---------------- fused sampled pipeline: R9 structure, fp16 weight ring ----------------
#define O_NCT 0
#define O_A2  4352
#define O_XT  5632
#define O_HT  14080
#define O_WFL 22528          // float count of activation region
#define WBUF_H 8320          // half units per ring buffer ([16][520])
#define SMEM_BYTES (O_WFL * 4 + 3 * WBUF_H * 2)   // 140032

__global__ __launch_bounds__(512, 1) void sample_kernel(
    const int* __restrict__ sidx_g, const float* __restrict__ gm,
    const float* __restrict__ be, const float* __restrict__ bd1,
    const float* __restrict__ Wd2, const float* __restrict__ bd2,
    float* __restrict__ out, int h)
{
    extern __shared__ float sm[];
    float* nct = sm + O_NCT;
    float* A2  = sm + O_A2;
    float* Xt  = sm + O_XT;
    float* Ht  = sm + O_HT;
    __half* Wsh = (__half*)(sm + O_WFL);
    __shared__ float gmrow[10];
    __shared__ int   sidx[64];

    const int t    = threadIdx.x;
    const int base = h * NS2 + blockIdx.x * 64;
    const uint32_t wsh_u = (uint32_t)__cvta_generic_to_shared(Wsh);

    if (t < 64) sidx[t] = sidx_g[base + t];
    if (t < 10) gmrow[t] = gm[(base >> 10) * 10 + t];

    auto prefetch = [&](int c2) {
        uint32_t db = wsh_u + (uint32_t)((c2 % 3) * WBUF_H) * 2;
        if (c2 < 4) {
            if (t < 256) {
                int idx = t * 8; int kk = idx >> 7, n = idx & 127;
                cp16(db + (uint32_t)(kk * 520 + n) * 2, g_Weh + c2 * 2048 + idx);
            }
        } else if (c2 < 36) {
#pragma unroll
            for (int ii = 0; ii < 2; ii++) {
                int idx = (ii * 512 + t) * 8; int kk = idx >> 9, n = idx & 511;
                cp16(db + (uint32_t)(kk * 520 + n) * 2,
                     g_Wlh + (size_t)(c2 - 4) * 8192 + idx);
            }
        } else if (c2 < 52) {
            if (t < 128) {
                int idx = t * 8; int kk = idx >> 6, n = idx & 63;
                cp16(db + (uint32_t)(kk * 520 + n) * 2,
                     g_Wd1h + (c2 - 36) * 1024 + idx);
            }
        }
        CP_COMMIT();
    };
    prefetch(0);
    prefetch(1);

    __syncthreads();

    float* out_nc = out;
    float* out_h1 = out + (size_t)NS * 64;
    float* out_c1 = out_h1 + (size_t)NS * 128;
    float* out_h2 = out_c1 + (size_t)NS * 128;
    float* out_c2 = out_h2 + (size_t)NS * 128;
    float* out_y  = out_c2 + (size_t)NS * 128;

    for (int idx = t; idx < 64 * 64; idx += 512) {
        int r = idx >> 6, c = idx & 63;
        float v = g_conv[(size_t)sidx[r] * 64 + c];
        nct[r * 68 + c] = tf32v(v);
        out_nc[(size_t)(base + r) * 64 + c] = v;
    }
    for (int idx = t; idx < 64 * 20; idx += 512) {
        int r = idx / 20, kk = idx - r * 20;
        A2[idx] = (kk < 10) ? tf32v(g_conv[(size_t)sidx[r] * 64 + 54 + kk]) : 0.f;
    }
    __syncthreads();

    const int w    = t >> 5;
    const int lane = t & 31;
    const int g8   = lane >> 2;
    const int cc   = lane & 3;
    const int j0   = w * 8;
    const int col0 = j0 + 2 * cc, col1 = col0 + 1;

    float acc[64];
#pragma unroll
    for (int i = 0; i < 64; i++) acc[i] = 0.f;

    // encoder chunks 0..3
#pragma unroll 1
    for (int c = 0; c < 4; c++) {
        CP_WAIT(1);
        __syncthreads();
        prefetch(c + 2);
        const __half* wb = Wsh + (c % 3) * WBUF_H;
#pragma unroll
        for (int ks = 0; ks < 2; ks++) {
            int k0 = c * 16 + ks * 8;
            uint32_t b0 = ldh(&wb[(ks * 8 + cc) * 520 + j0 + g8]);
            uint32_t b1 = ldh(&wb[(ks * 8 + cc + 4) * 520 + j0 + g8]);
#pragma unroll
            for (int mt = 0; mt < 4; mt++) {
                int r0 = mt * 16 + g8;
                uint32_t a[4];
                a[0] = ldb(&nct[r0 * 68 + k0 + cc]);
                a[1] = ldb(&nct[(r0 + 8) * 68 + k0 + cc]);
                a[2] = ldb(&nct[r0 * 68 + k0 + cc + 4]);
                a[3] = ldb(&nct[(r0 + 8) * 68 + k0 + cc + 4]);
                mma8(acc + mt * 4, a, b0, b1);
            }
        }
    }

    // gm-correction mma + encoder epilogue (We rows 54..63 = buffer0 rows 6..15)
    {
        const __half* wb = Wsh;
#pragma unroll
        for (int ks = 0; ks < 2; ks++) {
            int k0 = ks * 8;
            uint32_t b0 = ldh(&wb[(6 + k0 + cc) * 520 + j0 + g8]);
            uint32_t b1 = ldh(&wb[(6 + k0 + cc + 4) * 520 + j0 + g8]);
#pragma unroll
            for (int mt = 0; mt < 4; mt++) {
                int r0 = mt * 16 + g8;
                uint32_t a[4];
                a[0] = ldb(&A2[r0 * 20 + k0 + cc]);
                a[1] = ldb(&A2[(r0 + 8) * 20 + k0 + cc]);
                a[2] = ldb(&A2[r0 * 20 + k0 + cc + 4]);
                a[3] = ldb(&A2[(r0 + 8) * 20 + k0 + cc + 4]);
                mma8(acc + 16 + mt * 4, a, b0, b1);
            }
        }
        float be0 = be[col0], be1 = be[col1];
        float gs0 = 0.f, gs1 = 0.f;
#pragma unroll
        for (int k = 0; k < 10; k++) {
            gs0 = fmaf(gmrow[k], __half2float(wb[(6 + k) * 520 + col0]), gs0);
            gs1 = fmaf(gmrow[k], __half2float(wb[(6 + k) * 520 + col1]), gs1);
        }
#pragma unroll
        for (int mt = 0; mt < 4; mt++) {
#pragma unroll
            for (int pp = 0; pp < 2; pp++) {
                int row = mt * 16 + g8 + pp * 8;
                float hp0 = acc[mt * 4 + pp * 2],      hp1 = acc[mt * 4 + pp * 2 + 1];
                float cr0 = acc[16 + mt * 4 + pp * 2], cr1 = acc[16 + mt * 4 + pp * 2 + 1];
                *(float2*)(Xt + row * 132 + col0) =
                    make_float2(tf32v(fmaxf(hp0 - cr0 + gs0 + be0, 0.f)),
                                tf32v(fmaxf(hp1 - cr1 + gs1 + be1, 0.f)));
                *(float2*)(Ht + row * 132 + col0) =
                    make_float2(tf32v(fmaxf(hp0 + be0, 0.f)),
                                tf32v(fmaxf(hp1 + be1, 0.f)));
            }
        }
#pragma unroll
        for (int i = 0; i < 64; i++) acc[i] = 0.f;
    }
    __syncthreads();

    // LSTM cells: chunks 4..35
#pragma unroll 1
    for (int cell = 0; cell < 2; cell++) {
        const int cbase = 4 + cell * 16;
#pragma unroll 1
        for (int cl = 0; cl < 16; cl++) {
            const int c = cbase + cl;
            CP_WAIT(1);
            __syncthreads();
            prefetch(c + 2);
            const int kl = cl * 16;
            const __half* wb = Wsh + (c % 3) * WBUF_H;
#pragma unroll
            for (int ks = 0; ks < 2; ks++) {
                int kg = kl + ks * 8;
                const float* At_ = (kg < 128) ? (Xt + kg) : (Ht + (kg - 128));
                uint32_t afr[4][4];
#pragma unroll
                for (int mt = 0; mt < 4; mt++) {
                    int r0 = mt * 16 + g8;
                    afr[mt][0] = ldb(&At_[r0 * 132 + cc]);
                    afr[mt][1] = ldb(&At_[(r0 + 8) * 132 + cc]);
                    afr[mt][2] = ldb(&At_[r0 * 132 + cc + 4]);
                    afr[mt][3] = ldb(&At_[(r0 + 8) * 132 + cc + 4]);
                }
#pragma unroll
                for (int q = 0; q < 4; q++) {
                    int ncol = q * 128 + j0 + g8;
                    uint32_t b0 = ldh(&wb[(ks * 8 + cc) * 520 + ncol]);
                    uint32_t b1 = ldh(&wb[(ks * 8 + cc + 4) * 520 + ncol]);
#pragma unroll
                    for (int mt = 0; mt < 4; mt++)
                        mma8(acc + mt * 16 + q * 4, afr[mt], b0, b1);
                }
            }
        }

        __syncthreads();
        {
            const float* bc = g_bc + cell * 512;
            float* oH = cell ? out_h2 : out_h1;
            float* oC = cell ? out_c2 : out_c1;
#pragma unroll
            for (int mt = 0; mt < 4; mt++) {
#pragma unroll
                for (int pp = 0; pp < 2; pp++) {
                    int row = mt * 16 + g8 + pp * 8;
                    int ib  = mt * 16 + pp * 2;
                    float vi0 = acc[ib + 0]  + bc[col0],       vi1 = acc[ib + 1]  + bc[col1];
                    float vf0 = acc[ib + 4]  + bc[128 + col0], vf1 = acc[ib + 5]  + bc[128 + col1];
                    float vg0 = acc[ib + 8]  + bc[256 + col0], vg1 = acc[ib + 9]  + bc[256 + col1];
                    float vo0 = acc[ib + 12] + bc[384 + col0], vo1 = acc[ib + 13] + bc[384 + col1];
                    float cp0 = Ht[row * 132 + col0], cp1 = Ht[row * 132 + col1];
                    float cv0 = fsig(vf0) * cp0 + fsig(vi0) * ftanh(vg0);
                    float cv1 = fsig(vf1) * cp1 + fsig(vi1) * ftanh(vg1);
                    float hv0 = fsig(vo0) * ftanh(cv0);
                    float hv1 = fsig(vo1) * ftanh(cv1);
                    size_t gi = (size_t)(base + row) * 128 + col0;
                    *(float2*)(oH + gi) = make_float2(hv0, hv1);
                    *(float2*)(oC + gi) = make_float2(cv0, cv1);
                    if (cell == 0) {
                        float nx0 = (col0 >= 118) ? gmrow[col0 - 118] : hv0;
                        float nx1 = (col1 >= 118) ? gmrow[col1 - 118] : hv1;
                        *(float2*)(Xt + row * 132 + col0) = make_float2(tf32v(nx0), tf32v(nx1));
                    } else {
                        *(float2*)(Xt + row * 132 + col0) = make_float2(tf32v(hv0), tf32v(hv1));
                        *(float2*)(Ht + row * 132 + col0) = make_float2(tf32v(cv0), tf32v(cv1));
                    }
                }
            }
#pragma unroll
            for (int i = 0; i < 64; i++) acc[i] = 0.f;
        }
        __syncthreads();
    }

    // decoder: chunks 36..51
    {
        const int n0  = (w & 7) * 8;
        const int mt0 = (w >> 3) * 2;
#pragma unroll 1
        for (int dl = 0; dl < 16; dl++) {
            const int c = 36 + dl;
            CP_WAIT(1);
            __syncthreads();
            prefetch(c + 2);
            const __half* wb = Wsh + (c % 3) * WBUF_H;
#pragma unroll
            for (int ks = 0; ks < 2; ks++) {
                int kg = dl * 16 + ks * 8;
                const float* At_ = (kg < 128) ? (Xt + kg) : (Ht + (kg - 128));
                uint32_t b0 = ldh(&wb[(ks * 8 + cc) * 520 + n0 + g8]);
                uint32_t b1 = ldh(&wb[(ks * 8 + cc + 4) * 520 + n0 + g8]);
#pragma unroll
                for (int m = 0; m < 2; m++) {
                    int r0 = (mt0 + m) * 16 + g8;
                    uint32_t a[4];
                    a[0] = ldb(&At_[r0 * 132 + cc]);
                    a[1] = ldb(&At_[(r0 + 8) * 132 + cc]);
                    a[2] = ldb(&At_[r0 * 132 + cc + 4]);
                    a[3] = ldb(&At_[(r0 + 8) * 132 + cc + 4]);
                    mma8(acc + m * 4, a, b0, b1);
                }
            }
        }
        __syncthreads();
        int c0 = n0 + 2 * cc, c1 = c0 + 1;
        float b0 = bd1[c0], b1 = bd1[c1];
#pragma unroll
        for (int m = 0; m < 2; m++) {
#pragma unroll
            for (int pp = 0; pp < 2; pp++) {
                int row = (mt0 + m) * 16 + g8 + pp * 8;
                float v0 = fmaxf(acc[m * 4 + pp * 2]     + b0, 0.f);
                float v1 = fmaxf(acc[m * 4 + pp * 2 + 1] + b1, 0.f);
                *(float2*)(nct + row * 68 + c0) = make_float2(v0, v1);
            }
        }
    }
    __syncthreads();

    if (t < 384) {
        int r = t / 6, c = t - r * 6;
        float accy = bd2[c];
#pragma unroll
        for (int k = 0; k < 64; k++) accy = fmaf(nct[r * 68 + k], Wd2[k * 6 + c], accy);
        out_y[(size_t)(base + r) * 6 + c] = accy;
    }
}

// ----------------------------------------------------------------
extern "C" void kernel_launch(void* const* d_in, const int* in_sizes, int n_in,
                              void* d_out, int out_size)
{
    const float* x    = (const float*)d_in[0];
    const int*   ei   = (const int*)d_in[1];
    const float* ea   = (const float*)d_in[2];
    const int*   si   = (const int*)d_in[3];
    const float* gm   = (const float*)d_in[4];
    const float* Wm   = (const float*)d_in[5];
    const float* bm   = (const float*)d_in[6];
    const float* Wn   = (const float*)d_in[7];
    const float* bn   = (const float*)d_in[8];
    const float* We   = (const float*)d_in[9];
    const float* be_  = (const float*)d_in[10];
    const float* Wih0 = (const float*)d_in[11];
    const float* Whh0 = (const float*)d_in[12];
    const float* bih0 = (const float*)d_in[13];
    const float* bhh0 = (const float*)d_in[14];
    const float* Wih1 = (const float*)d_in[15];
    const float* Whh1 = (const float*)d_in[16];
    const float* bih1 = (const float*)d_in[17];
    const float* bhh1 = (const float*)d_in[18];
    const float* Wd1  = (const float*)d_in[19];
    const float* bd1  = (const float*)d_in[20];
    const float* Wd2  = (const float*)d_in[21];
    const float* bd2  = (const float*)d_in[22];
    float* out = (float*)d_out;

    static cudaStream_t s1 = nullptr;
    static cudaEvent_t evF = nullptr, evP = nullptr, evJ = nullptr;
    if (!s1) {
        cudaStreamCreateWithFlags(&s1, cudaStreamNonBlocking);
        cudaEventCreateWithFlags(&evF, cudaEventDisableTiming);
        cudaEventCreateWithFlags(&evP, cudaEventDisableTiming);
        cudaEventCreateWithFlags(&evJ, cudaEventDisableTiming);
        cudaFuncSetAttribute(sample_kernel,
                             cudaFuncAttributeMaxDynamicSharedMemorySize, SMEM_BYTES);
    }

    cudaEventRecord(evF, 0);
    cudaStreamWaitEvent(s1, evF, 0);

    // stream s1: prep then half-1 chain
    prep_kernel<<<1124, 256, 0, s1>>>(Wih0, Whh0, Wih1, Whh1, We, Wd1,
                                      bih0, bhh0, bih1, bhh1);
    cudaEventRecord(evP, s1);
    zero_tables_kernel<<<49, 256, 0, s1>>>(1);
    flag_zero_kernel<<<NS2 / 8, 256, 0, s1>>>(si, 1);
    compact_edges_kernel<<<NE2 / 256, 256, 0, s1>>>(ei, 1);
    compact_nodes_kernel<<<NN2 / 256, 256, 0, s1>>>(1);
    pre_kernel<<<NN / 256, 256, 0, s1>>>(x, Wm, bm, 1);
    edge_kernel<<<512, 256, 0, s1>>>(ea, Wm, 1);
    node_kernel<<<NS2 / 256, 256, 0, s1>>>(x, Wn, bn, 1);
    sample_kernel<<<NS2 / 64, 512, SMEM_BYTES, s1>>>(
        si, gm, be_, bd1, Wd2, bd2, out, 1);
    cudaEventRecord(evJ, s1);

    // default stream: half-0 chain
    zero_tables_kernel<<<49, 256>>>(0);
    flag_zero_kernel<<<NS2 / 8, 256>>>(si, 0);
    compact_edges_kernel<<<NE2 / 256, 256>>>(ei, 0);
    compact_nodes_kernel<<<NN2 / 256, 256>>>(0);
    pre_kernel<<<NN / 256, 256>>>(x, Wm, bm, 0);
    edge_kernel<<<512, 256>>>(ea, Wm, 0);
    node_kernel<<<NS2 / 256, 256>>>(x, Wn, bn, 0);
    cudaStreamWaitEvent(0, evP, 0);
    sample_kernel<<<NS2 / 64, 512, SMEM_BYTES>>>(
        si, gm, be_, bd1, Wd2, bd2, out, 0);

    cudaStreamWaitEvent(0, evJ, 0);
}

// round 14
// speedup vs baseline: 1.3109x; 1.0116x over previous
#include <cuda_runtime.h>
#include <cuda_fp16.h>
#include <math.h>
#include <stdint.h>

#define NN (64*4096)
#define NE (64*16384)
#define NS (64*1024)
#define NN2 (NN/2)
#define NE2 (NE/2)
#define NS2 (NS/2)
#define IN_F 26

typedef unsigned long long ull;

__device__ __align__(16) float g_agg[(size_t)NN * 64];
__device__ __align__(16) float g_conv[(size_t)NN * 64];
__device__ __align__(16) __half2 g_Ph[(size_t)NN * 64];   // [node][Psrc 32 | Pdst 32] half2
__device__ unsigned g_flagbits[NN / 32];
__device__ unsigned g_needsrc[NN / 32];
__device__ unsigned g_needdst[NN / 32];
__device__ int4  g_sde[NE];
__device__ int   g_nlist[NN];
__device__ int   g_plist[2 * NN];
__device__ int   g_cnt[8];
__device__ __align__(16) __half g_Wlh[512 * 512];
__device__ __align__(16) __half g_Weh[64 * 128];
__device__ __align__(16) __half g_Wd1h[256 * 64];
__device__ __align__(16) float  g_bc[2 * 512];

__device__ __forceinline__ ull pk(float lo, float hi) {
    ull r; asm("mov.b64 %0, {%1, %2};" : "=l"(r) : "f"(lo), "f"(hi)); return r;
}
__device__ __forceinline__ ull pk2(float v) { return pk(v, v); }
__device__ __forceinline__ float2 upk(ull v) {
    float2 r; asm("mov.b64 {%0, %1}, %2;" : "=f"(r.x), "=f"(r.y) : "l"(v)); return r;
}
__device__ __forceinline__ ull fma2(ull a, ull b, ull c) {
    ull d; asm("fma.rn.f32x2 %0, %1, %2, %3;" : "=l"(d) : "l"(a), "l"(b), "l"(c)); return d;
}
__device__ __forceinline__ ull add2(ull a, ull b) {
    ull d; asm("add.rn.f32x2 %0, %1, %2;" : "=l"(d) : "l"(a), "l"(b)); return d;
}
__device__ __forceinline__ float fsig(float x)  { return __fdividef(1.f, 1.f + __expf(-x)); }
__device__ __forceinline__ float ftanh(float x) { return 1.f - __fdividef(2.f, 1.f + __expf(2.f * x)); }

__device__ __forceinline__ float tf32v(float f) {
    uint32_t r; asm("cvt.rna.tf32.f32 %0, %1;" : "=r"(r) : "f"(f));
    return __uint_as_float(r);
}
__device__ __forceinline__ void mma8(float* d, const uint32_t* a, uint32_t b0, uint32_t b1) {
    asm volatile(
        "mma.sync.aligned.m16n8k8.row.col.f32.tf32.tf32.f32 "
        "{%0,%1,%2,%3}, {%4,%5,%6,%7}, {%8,%9}, {%0,%1,%2,%3};"
        : "+f"(d[0]), "+f"(d[1]), "+f"(d[2]), "+f"(d[3])
        : "r"(a[0]), "r"(a[1]), "r"(a[2]), "r"(a[3]), "r"(b0), "r"(b1));
}
__device__ __forceinline__ uint32_t ldb(const float* p) { return __float_as_uint(*p); }
__device__ __forceinline__ uint32_t ldh(const __half* p) {
    return __float_as_uint(__half2float(*p));
}
__device__ __forceinline__ uint32_t h2u(__half2 h) {
    uint32_t u; *(__half2*)&u = h; return u;
}
__device__ __forceinline__ void cp16(uint32_t dst, const void* src) {
    asm volatile("cp.async.cg.shared.global [%0], [%1], 16;" :: "r"(dst), "l"(src));
}
#define CP_COMMIT() asm volatile("cp.async.commit_group;")
#define CP_WAIT(n)  asm volatile("cp.async.wait_group " #n ";")
__device__ __forceinline__ void redv2(float* p, float a, float b) {
    asm volatile("red.global.add.v2.f32 [%0], {%1, %2};" :: "l"(p), "f"(a), "f"(b) : "memory");
}

// ---------------- prep: fp16 weight conversion ----------------
__global__ __launch_bounds__(256) void prep_kernel(
    const float* __restrict__ Wih0, const float* __restrict__ Whh0,
    const float* __restrict__ Wih1, const float* __restrict__ Whh1,
    const float* __restrict__ We,   const float* __restrict__ Wd1,
    const float* __restrict__ bih0, const float* __restrict__ bhh0,
    const float* __restrict__ bih1, const float* __restrict__ bhh1)
{
    int i = blockIdx.x * 256 + threadIdx.x;
    if (i < 262144) {
        int cell = i >> 17, r = (i >> 9) & 255, n = i & 511;
        const float* W = (r < 128) ? (cell ? Wih1 : Wih0) : (cell ? Whh1 : Whh0);
        g_Wlh[i] = __float2half(W[(r & 127) * 512 + n]);
    } else if (i < 270336) {
        int j = i - 262144; g_Weh[j] = __float2half(We[j]);
    } else if (i < 286720) {
        int j = i - 270336; g_Wd1h[j] = __float2half(Wd1[j]);
    } else if (i < 287744) {
        int j = i - 286720; int cell = j >> 9; int n = j & 511;
        g_bc[j] = cell ? (bih1[n] + bhh1[n]) : (bih0[n] + bhh0[n]);
    }
}

__global__ __launch_bounds__(256) void zero_tables_kernel(int h) {
    int i = blockIdx.x * 256 + threadIdx.x;
    int b = h * (NN2 / 32);
    if (i < 4096) g_flagbits[b + i] = 0u;
    else if (i < 8192) g_needsrc[b + i - 4096] = 0u;
    else if (i < 12288) g_needdst[b + i - 8192] = 0u;
    else if (i < 12292) g_cnt[h * 4 + i - 12288] = 0;
}

__global__ __launch_bounds__(256) void flag_zero_kernel(const int* __restrict__ si, int h) {
    int gw = blockIdx.x * 8 + (threadIdx.x >> 5);
    int l  = threadIdx.x & 31;
    int n  = si[h * NS2 + gw];
    if (l == 0) atomicOr(&g_flagbits[n >> 5], 1u << (n & 31));
    ((float2*)(g_agg + (size_t)n * 64))[l] = make_float2(0.f, 0.f);
}

__global__ __launch_bounds__(256) void compact_edges_kernel(const int* __restrict__ ei, int h) {
    int e = h * NE2 + blockIdx.x * 256 + threadIdx.x;
    int d = ei[NE + e];
    bool act = (g_flagbits[d >> 5] >> (d & 31)) & 1u;
    unsigned m = __ballot_sync(0xffffffffu, act);
    if (m) {
        int lane = threadIdx.x & 31;
        int leader = __ffs(m) - 1;
        int pos = 0;
        if (lane == leader) pos = atomicAdd(&g_cnt[h * 4], __popc(m));
        pos = __shfl_sync(0xffffffffu, pos, leader);
        pos += __popc(m & ((1u << lane) - 1));
        if (act) {
            int s = ei[e];
            g_sde[h * NE2 + pos] = make_int4(s, d, e, 0);
            atomicOr(&g_needsrc[s >> 5], 1u << (s & 31));
            atomicOr(&g_needdst[d >> 5], 1u << (d & 31));
        }
    }
}

__global__ __launch_bounds__(256) void compact_nodes_kernel(int h) {
    int n = h * NN2 + blockIdx.x * 256 + threadIdx.x;
    int lane = threadIdx.x & 31;
    {
        bool a = (g_flagbits[n >> 5] >> (n & 31)) & 1u;
        unsigned m = __ballot_sync(0xffffffffu, a);
        if (m) {
            int leader = __ffs(m) - 1;
            int pos = 0;
            if (lane == leader) pos = atomicAdd(&g_cnt[h * 4 + 1], __popc(m));
            pos = __shfl_sync(0xffffffffu, pos, leader);
            pos += __popc(m & ((1u << lane) - 1));
            if (a) g_nlist[h * NN2 + pos] = n;
        }
    }
    {
        bool a = (g_needsrc[n >> 5] >> (n & 31)) & 1u;
        unsigned m = __ballot_sync(0xffffffffu, a);
        if (m) {
            int leader = __ffs(m) - 1;
            int pos = 0;
            if (lane == leader) pos = atomicAdd(&g_cnt[h * 4 + 2], __popc(m));
            pos = __shfl_sync(0xffffffffu, pos, leader);
            pos += __popc(m & ((1u << lane) - 1));
            if (a) g_plist[h * NN + pos] = 2 * n;
        }
    }
    {
        bool a = (g_needdst[n >> 5] >> (n & 31)) & 1u;
        unsigned m = __ballot_sync(0xffffffffu, a);
        if (m) {
            int leader = __ffs(m) - 1;
            int pos = 0;
            if (lane == leader) pos = atomicAdd(&g_cnt[h * 4 + 2], __popc(m));
            pos = __shfl_sync(0xffffffffu, pos, leader);
            pos += __popc(m & ((1u << lane) - 1));
            if (a) g_plist[h * NN + pos] = 2 * n + 1;
        }
    }
}

// ---------------- pre: P halves stored fp16 ----------------
__global__ __launch_bounds__(256) void pre_kernel(
    const float* __restrict__ x, const float* __restrict__ Wm,
    const float* __restrict__ bm, int h)
{
    __shared__ float Ws[52 * 64];
    __shared__ float bs[64];
    for (int i = threadIdx.x; i < 52 * 64; i += 256) Ws[i] = Wm[i];
    if (threadIdx.x < 64) bs[threadIdx.x] = bm[threadIdx.x];
    __syncthreads();

    int i = blockIdx.x * 256 + threadIdx.x;
    if (i >= g_cnt[h * 4 + 2]) return;
    int job  = g_plist[h * NN + i];
    int n    = job >> 1;
    int half = job & 1;

    ull acc[32];
#pragma unroll
    for (int j = 0; j < 32; j++)
        acc[j] = half ? 0ull : pk(bs[2 * j], bs[2 * j + 1]);

    const float2* xr = (const float2*)(x + (size_t)n * IN_F);
    const int rbase = half * IN_F;
#pragma unroll
    for (int kk = 0; kk < 13; kk++) {
        float2 xv = xr[kk];
#pragma unroll
        for (int hh = 0; hh < 2; hh++) {
            ull v = pk2(hh ? xv.y : xv.x);
            const ulonglong2* wr = (const ulonglong2*)&Ws[(rbase + 2 * kk + hh) * 64];
#pragma unroll
            for (int j = 0; j < 16; j++) {
                ulonglong2 w = wr[j];
                acc[2 * j]     = fma2(v, w.x, acc[2 * j]);
                acc[2 * j + 1] = fma2(v, w.y, acc[2 * j + 1]);
            }
        }
    }
    uint4* dst = (uint4*)(g_Ph + (size_t)n * 64 + half * 32);
#pragma unroll
    for (int j = 0; j < 8; j++) {
        float2 a = upk(acc[4 * j]),     b = upk(acc[4 * j + 1]);
        float2 c = upk(acc[4 * j + 2]), d = upk(acc[4 * j + 3]);
        uint4 v;
        v.x = h2u(__floats2half2_rn(a.x, a.y));
        v.y = h2u(__floats2half2_rn(b.x, b.y));
        v.z = h2u(__floats2half2_rn(c.x, c.y));
        v.w = h2u(__floats2half2_rn(d.x, d.y));
        dst[j] = v;
    }
}

// ---------------- edges: fp16 P gathers ----------------
__global__ __launch_bounds__(256) void edge_kernel(const float* __restrict__ ea,
                                                   const float* __restrict__ Wm, int h)
{
    __shared__ float Ws[15 * 64];
    for (int i = threadIdx.x; i < 15 * 64; i += 256) Ws[i] = Wm[52 * 64 + i];
    __syncthreads();

    const int l  = threadIdx.x & 31;
    const int gw = blockIdx.x * 8 + (threadIdx.x >> 5);
    const int W  = gridDim.x * 8;
    const int ec = g_cnt[h * 4];

    for (int i = gw; i < ec; i += W) {
        int4 sde = g_sde[h * NE2 + i];
        float2 fs = __half22float2(g_Ph[(size_t)sde.x * 64 + l]);
        float2 fd = __half22float2(g_Ph[(size_t)sde.y * 64 + 32 + l]);
        ull acc = pk(fs.x + fd.x, fs.y + fd.y);
        const float* er = ea + (size_t)sde.z * 15;
#pragma unroll
        for (int k = 0; k < 15; k++) {
            ull w = *(const ull*)&Ws[k * 64 + 2 * l];
            acc = fma2(pk2(er[k]), w, acc);
        }
        float2 a = upk(acc);
        redv2(g_agg + (size_t)sde.y * 64 + 2 * l, fmaxf(a.x, 0.f), fmaxf(a.y, 0.f));
    }
}

__global__ __launch_bounds__(256) void node_kernel(
    const float* __restrict__ x, const float* __restrict__ Wn,
    const float* __restrict__ bn, int h)
{
    __shared__ float Ws[90 * 64];
    __shared__ float bs[64];
    for (int i = threadIdx.x; i < 90 * 64; i += 256) Ws[i] = Wn[i];
    if (threadIdx.x < 64) bs[threadIdx.x] = bn[threadIdx.x];
    __syncthreads();

    int i = blockIdx.x * 256 + threadIdx.x;
    if (i >= g_cnt[h * 4 + 1]) return;
    int n = g_nlist[h * NN2 + i];

    ull acc[32];
#pragma unroll
    for (int j = 0; j < 32; j++) acc[j] = pk(bs[2 * j], bs[2 * j + 1]);

    const float2* xr = (const float2*)(x + (size_t)n * IN_F);
#pragma unroll
    for (int kk = 0; kk < 13; kk++) {
        float2 xv = xr[kk];
#pragma unroll
        for (int hh = 0; hh < 2; hh++) {
            ull v = pk2(hh ? xv.y : xv.x);
            const ulonglong2* wr = (const ulonglong2*)&Ws[(2 * kk + hh) * 64];
#pragma unroll
            for (int j = 0; j < 16; j++) {
                ulonglong2 w = wr[j];
                acc[2 * j]     = fma2(v, w.x, acc[2 * j]);
                acc[2 * j + 1] = fma2(v, w.y, acc[2 * j + 1]);
            }
        }
    }
    const float4* ar = (const float4*)(g_agg + (size_t)n * 64);
#pragma unroll
    for (int kk = 0; kk < 16; kk++) {
        float4 av = ar[kk];
#pragma unroll
        for (int hh = 0; hh < 4; hh++) {
            float vf = hh == 0 ? av.x : hh == 1 ? av.y : hh == 2 ? av.z : av.w;
            ull v = pk2(vf);
            const ulonglong2* wr = (const ulonglong2*)&Ws[(IN_F + 4 * kk + hh) * 64];
#pragma unroll
            for (int j = 0; j < 16; j++) {
                ulonglong2 w = wr[j];
                acc[2 * j]     = fma2(v, w.x, acc[2 * j]);
                acc[2 * j + 1] = fma2(v, w.y, acc[2 * j + 1]);
            }
        }
    }
    float4* dst = (float4*)(g_conv + (size_t)n * 64);
#pragma unroll
    for (int j = 0; j < 16; j++) {
        float2 a = upk(acc[2 * j]), b = upk(acc[2 * j + 1]);
        dst[j] = make_float4(fmaxf(a.x, 0.f), fmaxf(a.y, 0.f),
                             fmaxf(b.x, 0.f), fmaxf(b.y, 0.f));
    }
}

// ---------------- fused sampled pipeline (validated R12 structure) ----------------
#define O_NCT 0
#define O_A2  4352
#define O_XT  5632
#define O_HT  14080
#define O_WFL 22528
#define WBUF_H 8320
#define SMEM_BYTES (O_WFL * 4 + 3 * WBUF_H * 2)   // 140032

__global__ __launch_bounds__(512, 1) void sample_kernel(
    const int* __restrict__ sidx_g, const float* __restrict__ gm,
    const float* __restrict__ be, const float* __restrict__ bd1,
    const float* __restrict__ Wd2, const float* __restrict__ bd2,
    float* __restrict__ out, int h)
{
    extern __shared__ float sm[];
    float* nct = sm + O_NCT;
    float* A2  = sm + O_A2;
    float* Xt  = sm + O_XT;
    float* Ht  = sm + O_HT;
    __half* Wsh = (__half*)(sm + O_WFL);
    __shared__ float gmrow[10];
    __shared__ int   sidx[64];

    const int t    = threadIdx.x;
    const int base = h * NS2 + blockIdx.x * 64;
    const uint32_t wsh_u = (uint32_t)__cvta_generic_to_shared(Wsh);

    if (t < 64) sidx[t] = sidx_g[base + t];
    if (t < 10) gmrow[t] = gm[(base >> 10) * 10 + t];

    auto prefetch = [&](int c2) {
        uint32_t db = wsh_u + (uint32_t)((c2 % 3) * WBUF_H) * 2;
        if (c2 < 4) {
            if (t < 256) {
                int idx = t * 8; int kk = idx >> 7, n = idx & 127;
                cp16(db + (uint32_t)(kk * 520 + n) * 2, g_Weh + c2 * 2048 + idx);
            }
        } else if (c2 < 36) {
#pragma unroll
            for (int ii = 0; ii < 2; ii++) {
                int idx = (ii * 512 + t) * 8; int kk = idx >> 9, n = idx & 511;
                cp16(db + (uint32_t)(kk * 520 + n) * 2,
                     g_Wlh + (size_t)(c2 - 4) * 8192 + idx);
            }
        } else if (c2 < 52) {
            if (t < 128) {
                int idx = t * 8; int kk = idx >> 6, n = idx & 63;
                cp16(db + (uint32_t)(kk * 520 + n) * 2,
                     g_Wd1h + (c2 - 36) * 1024 + idx);
            }
        }
        CP_COMMIT();
    };
    prefetch(0);
    prefetch(1);

    __syncthreads();

    float* out_nc = out;
    float* out_h1 = out + (size_t)NS * 64;
    float* out_c1 = out_h1 + (size_t)NS * 128;
    float* out_h2 = out_c1 + (size_t)NS * 128;
    float* out_c2 = out_h2 + (size_t)NS * 128;
    float* out_y  = out_c2 + (size_t)NS * 128;

    for (int idx = t; idx < 64 * 64; idx += 512) {
        int r = idx >> 6, c = idx & 63;
        float v = g_conv[(size_t)sidx[r] * 64 + c];
        nct[r * 68 + c] = tf32v(v);
        out_nc[(size_t)(base + r) * 64 + c] = v;
    }
    for (int idx = t; idx < 64 * 20; idx += 512) {
        int r = idx / 20, kk = idx - r * 20;
        A2[idx] = (kk < 10) ? tf32v(g_conv[(size_t)sidx[r] * 64 + 54 + kk]) : 0.f;
    }
    __syncthreads();

    const int w    = t >> 5;
    const int lane = t & 31;
    const int g8   = lane >> 2;
    const int cc   = lane & 3;
    const int j0   = w * 8;
    const int col0 = j0 + 2 * cc, col1 = col0 + 1;

    float acc[64];
#pragma unroll
    for (int i = 0; i < 64; i++) acc[i] = 0.f;

    // encoder chunks 0..3
#pragma unroll 1
    for (int c = 0; c < 4; c++) {
        CP_WAIT(1);
        __syncthreads();
        prefetch(c + 2);
        const __half* wb = Wsh + (c % 3) * WBUF_H;
#pragma unroll
        for (int ks = 0; ks < 2; ks++) {
            int k0 = c * 16 + ks * 8;
            uint32_t b0 = ldh(&wb[(ks * 8 + cc) * 520 + j0 + g8]);
            uint32_t b1 = ldh(&wb[(ks * 8 + cc + 4) * 520 + j0 + g8]);
#pragma unroll
            for (int mt = 0; mt < 4; mt++) {
                int r0 = mt * 16 + g8;
                uint32_t a[4];
                a[0] = ldb(&nct[r0 * 68 + k0 + cc]);
                a[1] = ldb(&nct[(r0 + 8) * 68 + k0 + cc]);
                a[2] = ldb(&nct[r0 * 68 + k0 + cc + 4]);
                a[3] = ldb(&nct[(r0 + 8) * 68 + k0 + cc + 4]);
                mma8(acc + mt * 4, a, b0, b1);
            }
        }
    }

    // gm-correction mma + encoder epilogue (We rows 54..63 = buffer0 rows 6..15)
    {
        const __half* wb = Wsh;
#pragma unroll
        for (int ks = 0; ks < 2; ks++) {
            int k0 = ks * 8;
            uint32_t b0 = ldh(&wb[(6 + k0 + cc) * 520 + j0 + g8]);
            uint32_t b1 = ldh(&wb[(6 + k0 + cc + 4) * 520 + j0 + g8]);
#pragma unroll
            for (int mt = 0; mt < 4; mt++) {
                int r0 = mt * 16 + g8;
                uint32_t a[4];
                a[0] = ldb(&A2[r0 * 20 + k0 + cc]);
                a[1] = ldb(&A2[(r0 + 8) * 20 + k0 + cc]);
                a[2] = ldb(&A2[r0 * 20 + k0 + cc + 4]);
                a[3] = ldb(&A2[(r0 + 8) * 20 + k0 + cc + 4]);
                mma8(acc + 16 + mt * 4, a, b0, b1);
            }
        }
        float be0 = be[col0], be1 = be[col1];
        float gs0 = 0.f, gs1 = 0.f;
#pragma unroll
        for (int k = 0; k < 10; k++) {
            gs0 = fmaf(gmrow[k], __half2float(wb[(6 + k) * 520 + col0]), gs0);
            gs1 = fmaf(gmrow[k], __half2float(wb[(6 + k) * 520 + col1]), gs1);
        }
#pragma unroll
        for (int mt = 0; mt < 4; mt++) {
#pragma unroll
            for (int pp = 0; pp < 2; pp++) {
                int row = mt * 16 + g8 + pp * 8;
                float hp0 = acc[mt * 4 + pp * 2],      hp1 = acc[mt * 4 + pp * 2 + 1];
                float cr0 = acc[16 + mt * 4 + pp * 2], cr1 = acc[16 + mt * 4 + pp * 2 + 1];
                *(float2*)(Xt + row * 132 + col0) =
                    make_float2(tf32v(fmaxf(hp0 - cr0 + gs0 + be0, 0.f)),
                                tf32v(fmaxf(hp1 - cr1 + gs1 + be1, 0.f)));
                *(float2*)(Ht + row * 132 + col0) =
                    make_float2(tf32v(fmaxf(hp0 + be0, 0.f)),
                                tf32v(fmaxf(hp1 + be1, 0.f)));
            }
        }
#pragma unroll
        for (int i = 0; i < 64; i++) acc[i] = 0.f;
    }
    __syncthreads();

    // LSTM cells: chunks 4..35
#pragma unroll 1
    for (int cell = 0; cell < 2; cell++) {
        const int cbase = 4 + cell * 16;
#pragma unroll 1
        for (int cl = 0; cl < 16; cl++) {
            const int c = cbase + cl;
            CP_WAIT(1);
            __syncthreads();
            prefetch(c + 2);
            const int kl = cl * 16;
            const __half* wb = Wsh + (c % 3) * WBUF_H;
#pragma unroll
            for (int ks = 0; ks < 2; ks++) {
                int kg = kl + ks * 8;
                const float* At_ = (kg < 128) ? (Xt + kg) : (Ht + (kg - 128));
                uint32_t afr[4][4];
#pragma unroll
                for (int mt = 0; mt < 4; mt++) {
                    int r0 = mt * 16 + g8;
                    afr[mt][0] = ldb(&At_[r0 * 132 + cc]);
                    afr[mt][1] = ldb(&At_[(r0 + 8) * 132 + cc]);
                    afr[mt][2] = ldb(&At_[r0 * 132 + cc + 4]);
                    afr[mt][3] = ldb(&At_[(r0 + 8) * 132 + cc + 4]);
                }
#pragma unroll
                for (int q = 0; q < 4; q++) {
                    int ncol = q * 128 + j0 + g8;
                    uint32_t b0 = ldh(&wb[(ks * 8 + cc) * 520 + ncol]);
                    uint32_t b1 = ldh(&wb[(ks * 8 + cc + 4) * 520 + ncol]);
#pragma unroll
                    for (int mt = 0; mt < 4; mt++)
                        mma8(acc + mt * 16 + q * 4, afr[mt], b0, b1);
                }
            }
        }

        __syncthreads();
        {
            const float* bc = g_bc + cell * 512;
            float* oH = cell ? out_h2 : out_h1;
            float* oC = cell ? out_c2 : out_c1;
#pragma unroll
            for (int mt = 0; mt < 4; mt++) {
#pragma unroll
                for (int pp = 0; pp < 2; pp++) {
                    int row = mt * 16 + g8 + pp * 8;
                    int ib  = mt * 16 + pp * 2;
                    float vi0 = acc[ib + 0]  + bc[col0],       vi1 = acc[ib + 1]  + bc[col1];
                    float vf0 = acc[ib + 4]  + bc[128 + col0], vf1 = acc[ib + 5]  + bc[128 + col1];
                    float vg0 = acc[ib + 8]  + bc[256 + col0], vg1 = acc[ib + 9]  + bc[256 + col1];
                    float vo0 = acc[ib + 12] + bc[384 + col0], vo1 = acc[ib + 13] + bc[384 + col1];
                    float cp0 = Ht[row * 132 + col0], cp1 = Ht[row * 132 + col1];
                    float cv0 = fsig(vf0) * cp0 + fsig(vi0) * ftanh(vg0);
                    float cv1 = fsig(vf1) * cp1 + fsig(vi1) * ftanh(vg1);
                    float hv0 = fsig(vo0) * ftanh(cv0);
                    float hv1 = fsig(vo1) * ftanh(cv1);
                    size_t gi = (size_t)(base + row) * 128 + col0;
                    *(float2*)(oH + gi) = make_float2(hv0, hv1);
                    *(float2*)(oC + gi) = make_float2(cv0, cv1);
                    if (cell == 0) {
                        float nx0 = (col0 >= 118) ? gmrow[col0 - 118] : hv0;
                        float nx1 = (col1 >= 118) ? gmrow[col1 - 118] : hv1;
                        *(float2*)(Xt + row * 132 + col0) = make_float2(tf32v(nx0), tf32v(nx1));
                    } else {
                        *(float2*)(Xt + row * 132 + col0) = make_float2(tf32v(hv0), tf32v(hv1));
                        *(float2*)(Ht + row * 132 + col0) = make_float2(tf32v(cv0), tf32v(cv1));
                    }
                }
            }
#pragma unroll
            for (int i = 0; i < 64; i++) acc[i] = 0.f;
        }
        __syncthreads();
    }

    // decoder: chunks 36..51
    {
        const int n0  = (w & 7) * 8;
        const int mt0 = (w >> 3) * 2;
#pragma unroll 1
        for (int dl = 0; dl < 16; dl++) {
            const int c = 36 + dl;
            CP_WAIT(1);
            __syncthreads();
            prefetch(c + 2);
            const __half* wb = Wsh + (c % 3) * WBUF_H;
#pragma unroll
            for (int ks = 0; ks < 2; ks++) {
                int kg = dl * 16 + ks * 8;
                const float* At_ = (kg < 128) ? (Xt + kg) : (Ht + (kg - 128));
                uint32_t b0 = ldh(&wb[(ks * 8 + cc) * 520 + n0 + g8]);
                uint32_t b1 = ldh(&wb[(ks * 8 + cc + 4) * 520 + n0 + g8]);
#pragma unroll
                for (int m = 0; m < 2; m++) {
                    int r0 = (mt0 + m) * 16 + g8;
                    uint32_t a[4];
                    a[0] = ldb(&At_[r0 * 132 + cc]);
                    a[1] = ldb(&At_[(r0 + 8) * 132 + cc]);
                    a[2] = ldb(&At_[r0 * 132 + cc + 4]);
                    a[3] = ldb(&At_[(r0 + 8) * 132 + cc + 4]);
                    mma8(acc + m * 4, a, b0, b1);
                }
            }
        }
        __syncthreads();
        int c0 = n0 + 2 * cc, c1 = c0 + 1;
        float b0 = bd1[c0], b1 = bd1[c1];
#pragma unroll
        for (int m = 0; m < 2; m++) {
#pragma unroll
            for (int pp = 0; pp < 2; pp++) {
                int row = (mt0 + m) * 16 + g8 + pp * 8;
                float v0 = fmaxf(acc[m * 4 + pp * 2]     + b0, 0.f);
                float v1 = fmaxf(acc[m * 4 + pp * 2 + 1] + b1, 0.f);
                *(float2*)(nct + row * 68 + c0) = make_float2(v0, v1);
            }
        }
    }
    __syncthreads();

    if (t < 384) {
        int r = t / 6, c = t - r * 6;
        float accy = bd2[c];
#pragma unroll
        for (int k = 0; k < 64; k++) accy = fmaf(nct[r * 68 + k], Wd2[k * 6 + c], accy);
        out_y[(size_t)(base + r) * 6 + c] = accy;
    }
}

// ----------------------------------------------------------------
extern "C" void kernel_launch(void* const* d_in, const int* in_sizes, int n_in,
                              void* d_out, int out_size)
{
    const float* x    = (const float*)d_in[0];
    const int*   ei   = (const int*)d_in[1];
    const float* ea   = (const float*)d_in[2];
    const int*   si   = (const int*)d_in[3];
    const float* gm   = (const float*)d_in[4];
    const float* Wm   = (const float*)d_in[5];
    const float* bm   = (const float*)d_in[6];
    const float* Wn   = (const float*)d_in[7];
    const float* bn   = (const float*)d_in[8];
    const float* We   = (const float*)d_in[9];
    const float* be_  = (const float*)d_in[10];
    const float* Wih0 = (const float*)d_in[11];
    const float* Whh0 = (const float*)d_in[12];
    const float* bih0 = (const float*)d_in[13];
    const float* bhh0 = (const float*)d_in[14];
    const float* Wih1 = (const float*)d_in[15];
    const float* Whh1 = (const float*)d_in[16];
    const float* bih1 = (const float*)d_in[17];
    const float* bhh1 = (const float*)d_in[18];
    const float* Wd1  = (const float*)d_in[19];
    const float* bd1  = (const float*)d_in[20];
    const float* Wd2  = (const float*)d_in[21];
    const float* bd2  = (const float*)d_in[22];
    float* out = (float*)d_out;

    static cudaStream_t s1 = nullptr, s2 = nullptr;
    static cudaEvent_t evF = nullptr, evP = nullptr, evJ = nullptr;
    if (!s1) {
        cudaStreamCreateWithFlags(&s1, cudaStreamNonBlocking);
        cudaStreamCreateWithFlags(&s2, cudaStreamNonBlocking);
        cudaEventCreateWithFlags(&evF, cudaEventDisableTiming);
        cudaEventCreateWithFlags(&evP, cudaEventDisableTiming);
        cudaEventCreateWithFlags(&evJ, cudaEventDisableTiming);
        cudaFuncSetAttribute(sample_kernel,
                             cudaFuncAttributeMaxDynamicSharedMemorySize, SMEM_BYTES);
    }

    cudaEventRecord(evF, 0);
    cudaStreamWaitEvent(s1, evF, 0);
    cudaStreamWaitEvent(s2, evF, 0);

    // stream s2: weight prep only
    prep_kernel<<<1124, 256, 0, s2>>>(Wih0, Whh0, Wih1, Whh1, We, Wd1,
                                      bih0, bhh0, bih1, bhh1);
    cudaEventRecord(evP, s2);

    // stream s1: half-1 chain
    zero_tables_kernel<<<49, 256, 0, s1>>>(1);
    flag_zero_kernel<<<NS2 / 8, 256, 0, s1>>>(si, 1);
    compact_edges_kernel<<<NE2 / 256, 256, 0, s1>>>(ei, 1);
    compact_nodes_kernel<<<NN2 / 256, 256, 0, s1>>>(1);
    pre_kernel<<<NN / 256, 256, 0, s1>>>(x, Wm, bm, 1);
    edge_kernel<<<512, 256, 0, s1>>>(ea, Wm, 1);
    node_kernel<<<NS2 / 256, 256, 0, s1>>>(x, Wn, bn, 1);
    cudaStreamWaitEvent(s1, evP, 0);
    sample_kernel<<<NS2 / 64, 512, SMEM_BYTES, s1>>>(
        si, gm, be_, bd1, Wd2, bd2, out, 1);
    cudaEventRecord(evJ, s1);

    // default stream: half-0 chain
    zero_tables_kernel<<<49, 256>>>(0);
    flag_zero_kernel<<<NS2 / 8, 256>>>(si, 0);
    compact_edges_kernel<<<NE2 / 256, 256>>>(ei, 0);
    compact_nodes_kernel<<<NN2 / 256, 256>>>(0);
    pre_kernel<<<NN / 256, 256>>>(x, Wm, bm, 0);
    edge_kernel<<<512, 256>>>(ea, Wm, 0);
    node_kernel<<<NS2 / 256, 256>>>(x, Wn, bn, 0);
    cudaStreamWaitEvent(0, evP, 0);
    sample_kernel<<<NS2 / 64, 512, SMEM_BYTES>>>(
        si, gm, be_, bd1, Wd2, bd2, out, 0);

    cudaStreamWaitEvent(0, evJ, 0);
}